// round 4
// baseline (speedup 1.0000x reference)
#include <cuda_runtime.h>
#include <cuda_bf16.h>
#include <cstdint>

// CrossAttention B=8, SQ=SK=2048, DIM=1024, fp32 in/out.
// All GEMMs: mma.sync m16n8k16 bf16->fp32, 2-way bf16 split (3 passes),
// pass-outermost MMA order (RAW distance 16), 4-stage cp.async pipeline,
// one barrier per k-tile.

#define DIMc 1024
#define NB   8
#define SQc  2048
#define SKc  2048

#define NXQ ((size_t)NB * SQc * DIMc)   // 16M
#define NS  ((size_t)NB * SQc * SKc)    // 33.5M

__device__ __align__(128) __nv_bfloat16 g_xh[NXQ],  g_xl[NXQ];
__device__ __align__(128) __nv_bfloat16 g_ch[NXQ],  g_cl[NXQ];
__device__ __align__(128) __nv_bfloat16 g_Wqh[DIMc*DIMc], g_Wql[DIMc*DIMc];
__device__ __align__(128) __nv_bfloat16 g_Wkh[DIMc*DIMc], g_Wkl[DIMc*DIMc];
__device__ __align__(128) __nv_bfloat16 g_Wvh[DIMc*DIMc], g_Wvl[DIMc*DIMc];
__device__ __align__(128) __nv_bfloat16 g_Qh[NXQ],  g_Ql[NXQ];
__device__ __align__(128) __nv_bfloat16 g_Kh[NXQ],  g_Kl[NXQ];
__device__ __align__(128) __nv_bfloat16 g_Vth[NXQ], g_Vtl[NXQ];
__device__ __align__(128) float         g_S[NS];
__device__ __align__(128) __nv_bfloat16 g_Ph[NS],   g_Pl[NS];

// ---------------- helpers ----------------
__device__ __forceinline__ uint32_t smem_u32(const void* p) {
    uint32_t a;
    asm("{ .reg .u64 t; cvta.to.shared.u64 t, %1; cvt.u32.u64 %0, t; }"
        : "=r"(a) : "l"(p));
    return a;
}
// pack: low half = bf16(lo), high half = bf16(hi)
__device__ __forceinline__ uint32_t cvt2(float lo, float hi) {
    uint32_t r;
    asm("cvt.rn.bf16x2.f32 %0, %1, %2;" : "=r"(r) : "f"(hi), "f"(lo));
    return r;
}
__device__ __forceinline__ void cp16(uint32_t dst, const void* src) {
    asm volatile("cp.async.cg.shared.global [%0], [%1], 16;"
                 :: "r"(dst), "l"(src));
}
__device__ __forceinline__ void ldsm4(uint32_t* r, uint32_t a) {
    asm volatile("ldmatrix.sync.aligned.m8n8.x4.shared.b16 {%0,%1,%2,%3}, [%4];"
                 : "=r"(r[0]), "=r"(r[1]), "=r"(r[2]), "=r"(r[3]) : "r"(a));
}
__device__ __forceinline__ void mma16816(float* d, const uint32_t* a,
                                         const uint32_t* b) {
    asm volatile(
        "mma.sync.aligned.m16n8k16.row.col.f32.bf16.bf16.f32 "
        "{%0,%1,%2,%3}, {%4,%5,%6,%7}, {%8,%9}, {%0,%1,%2,%3};"
        : "+f"(d[0]), "+f"(d[1]), "+f"(d[2]), "+f"(d[3])
        : "r"(a[0]), "r"(a[1]), "r"(a[2]), "r"(a[3]), "r"(b[0]), "r"(b[1]));
}

constexpr int STAGES  = 4;
constexpr int TSTRIDE = 40;                       // padded bf16 elems per row
constexpr int TILE_B  = 128 * TSTRIDE * 2;        // 10240 B per tile
constexpr int STG_B   = 4 * TILE_B;               // 40960 B per stage
constexpr int SMEM_B  = STAGES * STG_B;           // 163840 B

// ---------------- GEMM: C[M,N] = alpha * A[M,K] @ B[N,K]^T (+bias) ----------------
// OSPLIT=0: fp32 C out. OSPLIT=1: split bf16 out (Chi, Clo).
// bias_mode: 0 none, 1 per-column, 2 per-row.
template <int OSPLIT>
__global__ __launch_bounds__(256, 1)
void gemm_mma(const __nv_bfloat16* __restrict__ Ah, const __nv_bfloat16* __restrict__ Al,
              const __nv_bfloat16* __restrict__ Bh, const __nv_bfloat16* __restrict__ Bl,
              const float* __restrict__ bias, int bias_mode,
              float* __restrict__ C,
              __nv_bfloat16* __restrict__ Chi, __nv_bfloat16* __restrict__ Clo,
              int M, int N, int K, float alpha,
              long long sA, long long sB, long long sC)
{
    extern __shared__ __align__(1024) char smem[];
    const uint32_t tb = smem_u32(smem);

    const int tid  = threadIdx.x;
    const int lane = tid & 31;
    const int wid  = tid >> 5;
    const int wm   = wid & 3;        // 4 warps along M (32 rows each)
    const int wn   = wid >> 2;       // 2 warps along N (64 cols each)

    const long long bm = (long long)blockIdx.y * 128;
    const long long bn = (long long)blockIdx.x * 128;
    Ah += (long long)blockIdx.z * sA + bm * K;
    Al += (long long)blockIdx.z * sA + bm * K;
    Bh += (long long)blockIdx.z * sB + bn * K;
    Bl += (long long)blockIdx.z * sB + bn * K;

    const int ktot = K >> 5;

    // cp.async tile loader: 512 chunks of 16B per array, 2 per thread
    auto load_tile = [&](int kt) {
        const int k0 = kt << 5;
        const uint32_t sbase = tb + (uint32_t)(kt % STAGES) * STG_B;
        #pragma unroll
        for (int rep = 0; rep < 2; ++rep) {
            const int ch  = tid + rep * 256;
            const int row = ch >> 2;
            const int c   = ch & 3;
            const size_t g = (size_t)row * K + k0 + c * 8;
            const uint32_t s = sbase + (uint32_t)(row * TSTRIDE + c * 8) * 2;
            cp16(s,              Ah + g);
            cp16(s + TILE_B,     Al + g);
            cp16(s + 2 * TILE_B, Bh + g);
            cp16(s + 3 * TILE_B, Bl + g);
        }
    };

    // ldmatrix per-lane offsets
    const int a_r = (lane & 7) + ((lane >> 3) & 1) * 8;  // row within 16
    const int a_k = (lane >> 4) * 8;                     // 0 / 8
    const int b_n = (lane & 7) + ((lane >> 4) & 1) * 8;  // row within 16 (n)
    const int b_k = ((lane >> 3) & 1) * 8;               // 0 / 8

    float acc[2][8][4] = {};

    #pragma unroll
    for (int s = 0; s < STAGES - 1; ++s) {
        load_tile(s);
        asm volatile("cp.async.commit_group;" ::: "memory");
    }

    #pragma unroll 1
    for (int kt = 0; kt < ktot; ++kt) {
        asm volatile("cp.async.wait_group %0;" :: "n"(STAGES - 2) : "memory");
        __syncthreads();

        // prefetch next tile first (writes stage (kt-1)%4: all readers passed
        // the barrier above having finished compute(kt-1))
        if (kt + STAGES - 1 < ktot) load_tile(kt + STAGES - 1);
        asm volatile("cp.async.commit_group;" ::: "memory");

        const uint32_t sA0 = tb + (uint32_t)(kt % STAGES) * STG_B;
        #pragma unroll
        for (int k16 = 0; k16 < 2; ++k16) {
            uint32_t aH[2][4], aL[2][4], bH[4][4], bL[4][4];
            #pragma unroll
            for (int mt = 0; mt < 2; ++mt) {
                const uint32_t off =
                    (uint32_t)((wm * 32 + mt * 16 + a_r) * TSTRIDE + k16 * 16 + a_k) * 2;
                ldsm4(aH[mt], sA0 + off);
                ldsm4(aL[mt], sA0 + TILE_B + off);
            }
            #pragma unroll
            for (int j = 0; j < 4; ++j) {
                const uint32_t off =
                    (uint32_t)((wn * 64 + j * 16 + b_n) * TSTRIDE + k16 * 16 + b_k) * 2;
                ldsm4(bH[j], sA0 + 2 * TILE_B + off);
                ldsm4(bL[j], sA0 + 3 * TILE_B + off);
            }
            // pass-outermost: same accumulator revisited only every 16 MMAs
            #pragma unroll
            for (int p = 0; p < 3; ++p) {
                #pragma unroll
                for (int mt = 0; mt < 2; ++mt) {
                    #pragma unroll
                    for (int j = 0; j < 4; ++j) {
                        const uint32_t* ua = (p == 2) ? aL[mt] : aH[mt];
                        const uint32_t* ub = (p == 1) ? bL[j]  : bH[j];
                        mma16816(acc[mt][2 * j],     ua, ub);
                        mma16816(acc[mt][2 * j + 1], ua, ub + 2);
                    }
                }
            }
        }
    }

    // epilogue
    const int gr = lane >> 2;
    const int c2 = (lane & 3) * 2;
    #pragma unroll
    for (int mt = 0; mt < 2; ++mt) {
        #pragma unroll
        for (int nt = 0; nt < 8; ++nt) {
            const long long m0 = bm + wm * 32 + mt * 16 + gr;
            const long long n  = bn + wn * 64 + nt * 8 + c2;
            const float* a4 = acc[mt][nt];
            float v0 = a4[0] * alpha, v1 = a4[1] * alpha;
            float v2 = a4[2] * alpha, v3 = a4[3] * alpha;
            if (bias_mode == 1) {
                const float b0 = bias[n], b1 = bias[n + 1];
                v0 += b0; v1 += b1; v2 += b0; v3 += b1;
            } else if (bias_mode == 2) {
                const float b0 = bias[m0], b1 = bias[m0 + 8];
                v0 += b0; v1 += b0; v2 += b1; v3 += b1;
            }
            if (OSPLIT == 0) {
                float* Cb = C + (long long)blockIdx.z * sC;
                *(float2*)(Cb + m0 * N + n)       = make_float2(v0, v1);
                *(float2*)(Cb + (m0 + 8) * N + n) = make_float2(v2, v3);
            } else {
                __nv_bfloat16* Hb = Chi + (long long)blockIdx.z * sC;
                __nv_bfloat16* Lb = Clo + (long long)blockIdx.z * sC;
                uint32_t hp = cvt2(v0, v1);
                float h0 = __uint_as_float(hp << 16);
                float h1 = __uint_as_float(hp & 0xFFFF0000u);
                uint32_t lp = cvt2(v0 - h0, v1 - h1);
                *(uint32_t*)(Hb + m0 * N + n) = hp;
                *(uint32_t*)(Lb + m0 * N + n) = lp;
                hp = cvt2(v2, v3);
                h0 = __uint_as_float(hp << 16);
                h1 = __uint_as_float(hp & 0xFFFF0000u);
                lp = cvt2(v2 - h0, v3 - h1);
                *(uint32_t*)(Hb + (m0 + 8) * N + n) = hp;
                *(uint32_t*)(Lb + (m0 + 8) * N + n) = lp;
            }
        }
    }
}

// ---------------- fp32 -> split bf16 ----------------
__global__ __launch_bounds__(256)
void split2(const float4* __restrict__ in, uint2* __restrict__ hi,
            uint2* __restrict__ lo, int n4)
{
    int i = blockIdx.x * 256 + threadIdx.x;
    if (i >= n4) return;
    float4 v = in[i];
    uint32_t h01 = cvt2(v.x, v.y);
    uint32_t h23 = cvt2(v.z, v.w);
    float r0 = v.x - __uint_as_float(h01 << 16);
    float r1 = v.y - __uint_as_float(h01 & 0xFFFF0000u);
    float r2 = v.z - __uint_as_float(h23 << 16);
    float r3 = v.w - __uint_as_float(h23 & 0xFFFF0000u);
    hi[i] = make_uint2(h01, h23);
    lo[i] = make_uint2(cvt2(r0, r1), cvt2(r2, r3));
}

// ---------------- softmax (fp32 in, split bf16 out) ----------------
__global__ __launch_bounds__(256)
void softmax_split(const float* __restrict__ S, __nv_bfloat16* __restrict__ Ph,
                   __nv_bfloat16* __restrict__ Pl)
{
    const long long row = blockIdx.x;
    const float* p = S + row * (long long)SKc;
    const int t = threadIdx.x;

    float v[8];
    float mx = -3.402823466e38f;
    #pragma unroll
    for (int i = 0; i < 8; i++) {
        v[i] = p[t + i * 256];
        mx = fmaxf(mx, v[i]);
    }
    __shared__ float shm[8], shs[8];
    #pragma unroll
    for (int o = 16; o > 0; o >>= 1)
        mx = fmaxf(mx, __shfl_xor_sync(0xffffffffu, mx, o));
    if ((t & 31) == 0) shm[t >> 5] = mx;
    __syncthreads();
    mx = shm[0];
    #pragma unroll
    for (int w = 1; w < 8; w++) mx = fmaxf(mx, shm[w]);

    float sum = 0.f;
    #pragma unroll
    for (int i = 0; i < 8; i++) { v[i] = expf(v[i] - mx); sum += v[i]; }
    #pragma unroll
    for (int o = 16; o > 0; o >>= 1)
        sum += __shfl_xor_sync(0xffffffffu, sum, o);
    if ((t & 31) == 0) shs[t >> 5] = sum;
    __syncthreads();
    float tot = 0.f;
    #pragma unroll
    for (int w = 0; w < 8; w++) tot += shs[w];

    const float inv = 1.0f / tot;
    __nv_bfloat16* ph = Ph + row * (long long)SKc;
    __nv_bfloat16* pl = Pl + row * (long long)SKc;
    #pragma unroll
    for (int i = 0; i < 8; i++) {
        const float pv = v[i] * inv;
        const __nv_bfloat16 h = __float2bfloat16(pv);
        ph[t + i * 256] = h;
        pl[t + i * 256] = __float2bfloat16(pv - __bfloat162float(h));
    }
}

// ---------------- launch ----------------
extern "C" void kernel_launch(void* const* d_in, const int* in_sizes, int n_in,
                              void* d_out, int out_size)
{
    const float* x   = (const float*)d_in[0];
    const float* ctx = (const float*)d_in[1];
    const float* Wq  = (const float*)d_in[2];
    const float* bq  = (const float*)d_in[3];
    const float* Wk  = (const float*)d_in[4];
    const float* bk  = (const float*)d_in[5];
    const float* Wv  = (const float*)d_in[6];
    const float* bv  = (const float*)d_in[7];
    float* out = (float*)d_out;

    __nv_bfloat16 *xh, *xl, *ch, *cl, *Wqh, *Wql, *Wkh, *Wkl, *Wvh, *Wvl;
    __nv_bfloat16 *Qh, *Ql, *Kh, *Kl, *Vth, *Vtl, *Ph, *Pl;
    float* S;
    cudaGetSymbolAddress((void**)&xh,  g_xh);  cudaGetSymbolAddress((void**)&xl,  g_xl);
    cudaGetSymbolAddress((void**)&ch,  g_ch);  cudaGetSymbolAddress((void**)&cl,  g_cl);
    cudaGetSymbolAddress((void**)&Wqh, g_Wqh); cudaGetSymbolAddress((void**)&Wql, g_Wql);
    cudaGetSymbolAddress((void**)&Wkh, g_Wkh); cudaGetSymbolAddress((void**)&Wkl, g_Wkl);
    cudaGetSymbolAddress((void**)&Wvh, g_Wvh); cudaGetSymbolAddress((void**)&Wvl, g_Wvl);
    cudaGetSymbolAddress((void**)&Qh,  g_Qh);  cudaGetSymbolAddress((void**)&Ql,  g_Ql);
    cudaGetSymbolAddress((void**)&Kh,  g_Kh);  cudaGetSymbolAddress((void**)&Kl,  g_Kl);
    cudaGetSymbolAddress((void**)&Vth, g_Vth); cudaGetSymbolAddress((void**)&Vtl, g_Vtl);
    cudaGetSymbolAddress((void**)&Ph,  g_Ph);  cudaGetSymbolAddress((void**)&Pl,  g_Pl);
    cudaGetSymbolAddress((void**)&S,   g_S);

    cudaFuncSetAttribute(gemm_mma<0>, cudaFuncAttributeMaxDynamicSharedMemorySize, SMEM_B);
    cudaFuncSetAttribute(gemm_mma<1>, cudaFuncAttributeMaxDynamicSharedMemorySize, SMEM_B);

    // split inputs
    const int n4x = (int)(NXQ / 4), n4w = DIMc * DIMc / 4;
    split2<<<(n4x + 255) / 256, 256>>>((const float4*)x,   (uint2*)xh,  (uint2*)xl,  n4x);
    split2<<<(n4x + 255) / 256, 256>>>((const float4*)ctx, (uint2*)ch,  (uint2*)cl,  n4x);
    split2<<<(n4w + 255) / 256, 256>>>((const float4*)Wq,  (uint2*)Wqh, (uint2*)Wql, n4w);
    split2<<<(n4w + 255) / 256, 256>>>((const float4*)Wk,  (uint2*)Wkh, (uint2*)Wkl, n4w);
    split2<<<(n4w + 255) / 256, 256>>>((const float4*)Wv,  (uint2*)Wvh, (uint2*)Wvl, n4w);

    const float scale = 0.03125f;   // 1/sqrt(1024)

    // Q = x @ Wq^T + bq  -> split
    gemm_mma<1><<<dim3(DIMc / 128, (NB * SQc) / 128, 1), 256, SMEM_B>>>(
        xh, xl, Wqh, Wql, bq, 1, nullptr, Qh, Ql,
        NB * SQc, DIMc, DIMc, 1.f, 0, 0, 0);
    // K = ctx @ Wk^T + bk -> split
    gemm_mma<1><<<dim3(DIMc / 128, (NB * SKc) / 128, 1), 256, SMEM_B>>>(
        ch, cl, Wkh, Wkl, bk, 1, nullptr, Kh, Kl,
        NB * SKc, DIMc, DIMc, 1.f, 0, 0, 0);
    // Vt = Wv @ ctx^T + bv(row) -> split   (per batch [1024, 2048])
    gemm_mma<1><<<dim3(SKc / 128, DIMc / 128, NB), 256, SMEM_B>>>(
        Wvh, Wvl, ch, cl, bv, 2, nullptr, Vth, Vtl,
        DIMc, SKc, DIMc, 1.f, 0, (long long)SKc * DIMc, (long long)DIMc * SKc);
    // S = (Q @ K^T)/32  (fp32)   per batch [2048, 2048]
    gemm_mma<0><<<dim3(SKc / 128, SQc / 128, NB), 256, SMEM_B>>>(
        Qh, Ql, Kh, Kl, nullptr, 0, S, nullptr, nullptr,
        SQc, SKc, DIMc, scale,
        (long long)SQc * DIMc, (long long)SKc * DIMc, (long long)SQc * SKc);
    // softmax -> split P
    softmax_split<<<NB * SQc, 256>>>(S, Ph, Pl);
    // O = P @ Vt^T (fp32)        per batch [2048, 1024]
    gemm_mma<0><<<dim3(DIMc / 128, SQc / 128, NB), 256, SMEM_B>>>(
        Ph, Pl, Vth, Vtl, nullptr, 0, out, nullptr, nullptr,
        SQc, DIMc, SKc, 1.f,
        (long long)SQc * SKc, (long long)DIMc * SKc, (long long)SQc * DIMc);
}

// round 7
// speedup vs baseline: 1.0120x; 1.0120x over previous
#include <cuda_runtime.h>
#include <cuda_bf16.h>
#include <cstdint>

// CrossAttention B=8, SQ=SK=2048, DIM=1024, fp32 in/out.
// All GEMMs: mma.sync m16n8k16 bf16->fp32, 2-way bf16 split (3 passes).
// 256x128 CTA tile (64x64 warptile), 3-stage cp.async pipeline.

#define DIMc 1024
#define NB   8
#define SQc  2048
#define SKc  2048

#define NXQ ((size_t)NB * SQc * DIMc)   // 16M
#define NS  ((size_t)NB * SQc * SKc)    // 33.5M

__device__ __align__(128) __nv_bfloat16 g_xh[NXQ],  g_xl[NXQ];
__device__ __align__(128) __nv_bfloat16 g_ch[NXQ],  g_cl[NXQ];
__device__ __align__(128) __nv_bfloat16 g_Wqh[DIMc*DIMc], g_Wql[DIMc*DIMc];
__device__ __align__(128) __nv_bfloat16 g_Wkh[DIMc*DIMc], g_Wkl[DIMc*DIMc];
__device__ __align__(128) __nv_bfloat16 g_Wvh[DIMc*DIMc], g_Wvl[DIMc*DIMc];
__device__ __align__(128) __nv_bfloat16 g_Qh[NXQ],  g_Ql[NXQ];
__device__ __align__(128) __nv_bfloat16 g_Kh[NXQ],  g_Kl[NXQ];
__device__ __align__(128) __nv_bfloat16 g_Vth[NXQ], g_Vtl[NXQ];
__device__ __align__(128) float         g_S[NS];
__device__ __align__(128) __nv_bfloat16 g_Ph[NS],   g_Pl[NS];

// ---------------- helpers ----------------
__device__ __forceinline__ uint32_t smem_u32(const void* p) {
    uint32_t a;
    asm("{ .reg .u64 t; cvta.to.shared.u64 t, %1; cvt.u32.u64 %0, t; }"
        : "=r"(a) : "l"(p));
    return a;
}
// pack: low half = bf16(lo), high half = bf16(hi)
__device__ __forceinline__ uint32_t cvt2(float lo, float hi) {
    uint32_t r;
    asm("cvt.rn.bf16x2.f32 %0, %1, %2;" : "=r"(r) : "f"(hi), "f"(lo));
    return r;
}
__device__ __forceinline__ void cp16(uint32_t dst, const void* src) {
    asm volatile("cp.async.cg.shared.global [%0], [%1], 16;"
                 :: "r"(dst), "l"(src));
}
__device__ __forceinline__ void ldsm4(uint32_t* r, uint32_t a) {
    asm volatile("ldmatrix.sync.aligned.m8n8.x4.shared.b16 {%0,%1,%2,%3}, [%4];"
                 : "=r"(r[0]), "=r"(r[1]), "=r"(r[2]), "=r"(r[3]) : "r"(a));
}
__device__ __forceinline__ void mma16816(float* d, const uint32_t* a,
                                         const uint32_t* b) {
    asm volatile(
        "mma.sync.aligned.m16n8k16.row.col.f32.bf16.bf16.f32 "
        "{%0,%1,%2,%3}, {%4,%5,%6,%7}, {%8,%9}, {%0,%1,%2,%3};"
        : "+f"(d[0]), "+f"(d[1]), "+f"(d[2]), "+f"(d[3])
        : "r"(a[0]), "r"(a[1]), "r"(a[2]), "r"(a[3]), "r"(b[0]), "r"(b[1]));
}

constexpr int TILE_M  = 256;
constexpr int TILE_N  = 128;
constexpr int STAGES  = 3;
constexpr int TSTRIDE = 40;                         // padded bf16 elems per row
constexpr int A_TILE_B = TILE_M * TSTRIDE * 2;      // 20480 B
constexpr int B_TILE_B = TILE_N * TSTRIDE * 2;      // 10240 B
constexpr int OFF_AH = 0;
constexpr int OFF_AL = A_TILE_B;
constexpr int OFF_BH = 2 * A_TILE_B;
constexpr int OFF_BL = 2 * A_TILE_B + B_TILE_B;
constexpr int STG_B  = 2 * A_TILE_B + 2 * B_TILE_B; // 61440 B
constexpr int SMEM_B = STAGES * STG_B;              // 184320 B

// ---------------- GEMM: C[M,N] = alpha * A[M,K] @ B[N,K]^T (+bias) ----------------
// OSPLIT=0: fp32 C out. OSPLIT=1: split bf16 out (Chi, Clo).
// bias_mode: 0 none, 1 per-column, 2 per-row.
template <int OSPLIT>
__global__ __launch_bounds__(256, 1)
void gemm_mma(const __nv_bfloat16* __restrict__ Ah, const __nv_bfloat16* __restrict__ Al,
              const __nv_bfloat16* __restrict__ Bh, const __nv_bfloat16* __restrict__ Bl,
              const float* __restrict__ bias, int bias_mode,
              float* __restrict__ C,
              __nv_bfloat16* __restrict__ Chi, __nv_bfloat16* __restrict__ Clo,
              int M, int N, int K, float alpha,
              long long sA, long long sB, long long sC)
{
    extern __shared__ __align__(1024) char smem[];
    const uint32_t tb = smem_u32(smem);

    const int tid  = threadIdx.x;
    const int lane = tid & 31;
    const int wid  = tid >> 5;
    const int wm   = wid & 3;        // 4 warps along M (64 rows each)
    const int wn   = wid >> 2;       // 2 warps along N (64 cols each)

    const long long bm = (long long)blockIdx.y * TILE_M;
    const long long bn = (long long)blockIdx.x * TILE_N;
    Ah += (long long)blockIdx.z * sA + bm * K;
    Al += (long long)blockIdx.z * sA + bm * K;
    Bh += (long long)blockIdx.z * sB + bn * K;
    Bl += (long long)blockIdx.z * sB + bn * K;

    const int ktot = K >> 5;

    // cp.async tile loader: A 1024 chunks/array (4 per thread), B 512 (2 per thread)
    auto load_tile = [&](int kt) {
        const int k0 = kt << 5;
        const uint32_t sbase = tb + (uint32_t)(kt % STAGES) * STG_B;
        #pragma unroll
        for (int rep = 0; rep < 4; ++rep) {
            const int ch  = tid + rep * 256;
            const int row = ch >> 2;
            const int c   = ch & 3;
            const size_t g = (size_t)row * K + k0 + c * 8;
            const uint32_t s = sbase + (uint32_t)(row * TSTRIDE + c * 8) * 2;
            cp16(s + OFF_AH, Ah + g);
            cp16(s + OFF_AL, Al + g);
        }
        #pragma unroll
        for (int rep = 0; rep < 2; ++rep) {
            const int ch  = tid + rep * 256;
            const int row = ch >> 2;
            const int c   = ch & 3;
            const size_t g = (size_t)row * K + k0 + c * 8;
            const uint32_t s = sbase + (uint32_t)(row * TSTRIDE + c * 8) * 2;
            cp16(s + OFF_BH, Bh + g);
            cp16(s + OFF_BL, Bl + g);
        }
    };

    // ldmatrix per-lane offsets
    const int a_r = (lane & 7) + ((lane >> 3) & 1) * 8;  // row within 16
    const int a_k = (lane >> 4) * 8;                     // 0 / 8
    const int b_n = (lane & 7) + ((lane >> 4) & 1) * 8;  // row within 16 (n)
    const int b_k = ((lane >> 3) & 1) * 8;               // 0 / 8

    float acc[4][8][4] = {};

    #pragma unroll
    for (int s = 0; s < STAGES - 1; ++s) {
        load_tile(s);
        asm volatile("cp.async.commit_group;" ::: "memory");
    }

    #pragma unroll 1
    for (int kt = 0; kt < ktot; ++kt) {
        asm volatile("cp.async.wait_group %0;" :: "n"(STAGES - 2) : "memory");
        __syncthreads();

        // prefetch next tile (stage being overwritten was consumed last iter)
        if (kt + STAGES - 1 < ktot) load_tile(kt + STAGES - 1);
        asm volatile("cp.async.commit_group;" ::: "memory");

        const uint32_t sA0 = tb + (uint32_t)(kt % STAGES) * STG_B;
        #pragma unroll
        for (int k16 = 0; k16 < 2; ++k16) {
            uint32_t aH[4][4], aL[4][4];
            #pragma unroll
            for (int mt = 0; mt < 4; ++mt) {
                const uint32_t off =
                    (uint32_t)((wm * 64 + mt * 16 + a_r) * TSTRIDE + k16 * 16 + a_k) * 2;
                ldsm4(aH[mt], sA0 + OFF_AH + off);
                ldsm4(aL[mt], sA0 + OFF_AL + off);
            }
            #pragma unroll
            for (int j = 0; j < 4; ++j) {
                uint32_t bH[4], bL[4];
                const uint32_t off =
                    (uint32_t)((wn * 64 + j * 16 + b_n) * TSTRIDE + k16 * 16 + b_k) * 2;
                ldsm4(bH, sA0 + OFF_BH + off);
                ldsm4(bL, sA0 + OFF_BL + off);
                #pragma unroll
                for (int p = 0; p < 3; ++p) {
                    const uint32_t* ub = (p == 1) ? bL : bH;
                    #pragma unroll
                    for (int mt = 0; mt < 4; ++mt) {
                        const uint32_t* ua = (p == 2) ? aL[mt] : aH[mt];
                        mma16816(acc[mt][2 * j],     ua, ub);
                        mma16816(acc[mt][2 * j + 1], ua, ub + 2);
                    }
                }
            }
        }
    }

    // epilogue
    const int gr = lane >> 2;
    const int c2 = (lane & 3) * 2;
    #pragma unroll
    for (int mt = 0; mt < 4; ++mt) {
        #pragma unroll
        for (int nt = 0; nt < 8; ++nt) {
            const long long m0 = bm + wm * 64 + mt * 16 + gr;
            const long long n  = bn + wn * 64 + nt * 8 + c2;
            const float* a4 = acc[mt][nt];
            float v0 = a4[0] * alpha, v1 = a4[1] * alpha;
            float v2 = a4[2] * alpha, v3 = a4[3] * alpha;
            if (bias_mode == 1) {
                const float b0 = bias[n], b1 = bias[n + 1];
                v0 += b0; v1 += b1; v2 += b0; v3 += b1;
            } else if (bias_mode == 2) {
                const float b0 = bias[m0], b1 = bias[m0 + 8];
                v0 += b0; v1 += b0; v2 += b1; v3 += b1;
            }
            if (OSPLIT == 0) {
                float* Cb = C + (long long)blockIdx.z * sC;
                *(float2*)(Cb + m0 * N + n)       = make_float2(v0, v1);
                *(float2*)(Cb + (m0 + 8) * N + n) = make_float2(v2, v3);
            } else {
                __nv_bfloat16* Hb = Chi + (long long)blockIdx.z * sC;
                __nv_bfloat16* Lb = Clo + (long long)blockIdx.z * sC;
                uint32_t hp = cvt2(v0, v1);
                float h0 = __uint_as_float(hp << 16);
                float h1 = __uint_as_float(hp & 0xFFFF0000u);
                uint32_t lp = cvt2(v0 - h0, v1 - h1);
                *(uint32_t*)(Hb + m0 * N + n) = hp;
                *(uint32_t*)(Lb + m0 * N + n) = lp;
                hp = cvt2(v2, v3);
                h0 = __uint_as_float(hp << 16);
                h1 = __uint_as_float(hp & 0xFFFF0000u);
                lp = cvt2(v2 - h0, v3 - h1);
                *(uint32_t*)(Hb + (m0 + 8) * N + n) = hp;
                *(uint32_t*)(Lb + (m0 + 8) * N + n) = lp;
            }
        }
    }
}

// ---------------- fp32 -> split bf16 ----------------
__global__ __launch_bounds__(256)
void split2(const float4* __restrict__ in, uint2* __restrict__ hi,
            uint2* __restrict__ lo, int n4)
{
    int i = blockIdx.x * 256 + threadIdx.x;
    if (i >= n4) return;
    float4 v = in[i];
    uint32_t h01 = cvt2(v.x, v.y);
    uint32_t h23 = cvt2(v.z, v.w);
    float r0 = v.x - __uint_as_float(h01 << 16);
    float r1 = v.y - __uint_as_float(h01 & 0xFFFF0000u);
    float r2 = v.z - __uint_as_float(h23 << 16);
    float r3 = v.w - __uint_as_float(h23 & 0xFFFF0000u);
    hi[i] = make_uint2(h01, h23);
    lo[i] = make_uint2(cvt2(r0, r1), cvt2(r2, r3));
}

// ---------------- softmax (fp32 in, split bf16 out) ----------------
__global__ __launch_bounds__(256)
void softmax_split(const float* __restrict__ S, __nv_bfloat16* __restrict__ Ph,
                   __nv_bfloat16* __restrict__ Pl)
{
    const long long row = blockIdx.x;
    const float* p = S + row * (long long)SKc;
    const int t = threadIdx.x;

    float v[8];
    float mx = -3.402823466e38f;
    #pragma unroll
    for (int i = 0; i < 8; i++) {
        v[i] = p[t + i * 256];
        mx = fmaxf(mx, v[i]);
    }
    __shared__ float shm[8], shs[8];
    #pragma unroll
    for (int o = 16; o > 0; o >>= 1)
        mx = fmaxf(mx, __shfl_xor_sync(0xffffffffu, mx, o));
    if ((t & 31) == 0) shm[t >> 5] = mx;
    __syncthreads();
    mx = shm[0];
    #pragma unroll
    for (int w = 1; w < 8; w++) mx = fmaxf(mx, shm[w]);

    float sum = 0.f;
    #pragma unroll
    for (int i = 0; i < 8; i++) { v[i] = expf(v[i] - mx); sum += v[i]; }
    #pragma unroll
    for (int o = 16; o > 0; o >>= 1)
        sum += __shfl_xor_sync(0xffffffffu, sum, o);
    if ((t & 31) == 0) shs[t >> 5] = sum;
    __syncthreads();
    float tot = 0.f;
    #pragma unroll
    for (int w = 0; w < 8; w++) tot += shs[w];

    const float inv = 1.0f / tot;
    __nv_bfloat16* ph = Ph + row * (long long)SKc;
    __nv_bfloat16* pl = Pl + row * (long long)SKc;
    #pragma unroll
    for (int i = 0; i < 8; i++) {
        const float pv = v[i] * inv;
        const __nv_bfloat16 h = __float2bfloat16(pv);
        ph[t + i * 256] = h;
        pl[t + i * 256] = __float2bfloat16(pv - __bfloat162float(h));
    }
}

// ---------------- launch ----------------
extern "C" void kernel_launch(void* const* d_in, const int* in_sizes, int n_in,
                              void* d_out, int out_size)
{
    const float* x   = (const float*)d_in[0];
    const float* ctx = (const float*)d_in[1];
    const float* Wq  = (const float*)d_in[2];
    const float* bq  = (const float*)d_in[3];
    const float* Wk  = (const float*)d_in[4];
    const float* bk  = (const float*)d_in[5];
    const float* Wv  = (const float*)d_in[6];
    const float* bv  = (const float*)d_in[7];
    float* out = (float*)d_out;

    __nv_bfloat16 *xh, *xl, *ch, *cl, *Wqh, *Wql, *Wkh, *Wkl, *Wvh, *Wvl;
    __nv_bfloat16 *Qh, *Ql, *Kh, *Kl, *Vth, *Vtl, *Ph, *Pl;
    float* S;
    cudaGetSymbolAddress((void**)&xh,  g_xh);  cudaGetSymbolAddress((void**)&xl,  g_xl);
    cudaGetSymbolAddress((void**)&ch,  g_ch);  cudaGetSymbolAddress((void**)&cl,  g_cl);
    cudaGetSymbolAddress((void**)&Wqh, g_Wqh); cudaGetSymbolAddress((void**)&Wql, g_Wql);
    cudaGetSymbolAddress((void**)&Wkh, g_Wkh); cudaGetSymbolAddress((void**)&Wkl, g_Wkl);
    cudaGetSymbolAddress((void**)&Wvh, g_Wvh); cudaGetSymbolAddress((void**)&Wvl, g_Wvl);
    cudaGetSymbolAddress((void**)&Qh,  g_Qh);  cudaGetSymbolAddress((void**)&Ql,  g_Ql);
    cudaGetSymbolAddress((void**)&Kh,  g_Kh);  cudaGetSymbolAddress((void**)&Kl,  g_Kl);
    cudaGetSymbolAddress((void**)&Vth, g_Vth); cudaGetSymbolAddress((void**)&Vtl, g_Vtl);
    cudaGetSymbolAddress((void**)&Ph,  g_Ph);  cudaGetSymbolAddress((void**)&Pl,  g_Pl);
    cudaGetSymbolAddress((void**)&S,   g_S);

    cudaFuncSetAttribute(gemm_mma<0>, cudaFuncAttributeMaxDynamicSharedMemorySize, SMEM_B);
    cudaFuncSetAttribute(gemm_mma<1>, cudaFuncAttributeMaxDynamicSharedMemorySize, SMEM_B);

    // split inputs
    const int n4x = (int)(NXQ / 4), n4w = DIMc * DIMc / 4;
    split2<<<(n4x + 255) / 256, 256>>>((const float4*)x,   (uint2*)xh,  (uint2*)xl,  n4x);
    split2<<<(n4x + 255) / 256, 256>>>((const float4*)ctx, (uint2*)ch,  (uint2*)cl,  n4x);
    split2<<<(n4w + 255) / 256, 256>>>((const float4*)Wq,  (uint2*)Wqh, (uint2*)Wql, n4w);
    split2<<<(n4w + 255) / 256, 256>>>((const float4*)Wk,  (uint2*)Wkh, (uint2*)Wkl, n4w);
    split2<<<(n4w + 255) / 256, 256>>>((const float4*)Wv,  (uint2*)Wvh, (uint2*)Wvl, n4w);

    const float scale = 0.03125f;   // 1/sqrt(1024)

    // Q = x @ Wq^T + bq  -> split
    gemm_mma<1><<<dim3(DIMc / TILE_N, (NB * SQc) / TILE_M, 1), 256, SMEM_B>>>(
        xh, xl, Wqh, Wql, bq, 1, nullptr, Qh, Ql,
        NB * SQc, DIMc, DIMc, 1.f, 0, 0, 0);
    // K = ctx @ Wk^T + bk -> split
    gemm_mma<1><<<dim3(DIMc / TILE_N, (NB * SKc) / TILE_M, 1), 256, SMEM_B>>>(
        ch, cl, Wkh, Wkl, bk, 1, nullptr, Kh, Kl,
        NB * SKc, DIMc, DIMc, 1.f, 0, 0, 0);
    // Vt = Wv @ ctx^T + bv(row) -> split   (per batch [1024, 2048])
    gemm_mma<1><<<dim3(SKc / TILE_N, DIMc / TILE_M, NB), 256, SMEM_B>>>(
        Wvh, Wvl, ch, cl, bv, 2, nullptr, Vth, Vtl,
        DIMc, SKc, DIMc, 1.f, 0, (long long)SKc * DIMc, (long long)DIMc * SKc);
    // S = (Q @ K^T)/32  (fp32)   per batch [2048, 2048]
    gemm_mma<0><<<dim3(SKc / TILE_N, SQc / TILE_M, NB), 256, SMEM_B>>>(
        Qh, Ql, Kh, Kl, nullptr, 0, S, nullptr, nullptr,
        SQc, SKc, DIMc, scale,
        (long long)SQc * DIMc, (long long)SKc * DIMc, (long long)SQc * SKc);
    // softmax -> split P
    softmax_split<<<NB * SQc, 256>>>(S, Ph, Pl);
    // O = P @ Vt^T (fp32)        per batch [2048, 1024]
    gemm_mma<0><<<dim3(DIMc / TILE_N, SQc / TILE_M, NB), 256, SMEM_B>>>(
        Ph, Pl, Vth, Vtl, nullptr, 0, out, nullptr, nullptr,
        SQc, DIMc, SKc, 1.f,
        (long long)SQc * SKc, (long long)DIMc * SKc, (long long)SQc * DIMc);
}

// round 8
// speedup vs baseline: 1.1853x; 1.1712x over previous
#include <cuda_runtime.h>
#include <cuda_fp16.h>
#include <cstdint>

// CrossAttention B=8, SQ=SK=2048, DIM=1024, fp32 in/out.
// All GEMMs: mma.sync m16n8k16 fp16->fp32, TWO passes via Ootomo scaled-residual
// split: h = fp16(x), t = fp16(h + 64*(x-h)).  A.B ~= acc1 + (acc2-acc1)/64
// where acc1 = Ah.Bh, acc2 = At.Bt  (captures both cross terms).

#define DIMc 1024
#define NB   8
#define SQc  2048
#define SKc  2048

#define NXQ ((size_t)NB * SQc * DIMc)   // 16.7M
#define NS  ((size_t)NB * SQc * SKc)    // 33.5M

__device__ __align__(128) __half g_xh[NXQ],  g_xt[NXQ];
__device__ __align__(128) __half g_ch[NXQ],  g_ct[NXQ];
__device__ __align__(128) __half g_Wqh[DIMc*DIMc], g_Wqt[DIMc*DIMc];
__device__ __align__(128) __half g_Wkh[DIMc*DIMc], g_Wkt[DIMc*DIMc];
__device__ __align__(128) __half g_Wvh[DIMc*DIMc], g_Wvt[DIMc*DIMc];
__device__ __align__(128) __half g_Qh[NXQ],  g_Qt[NXQ];
__device__ __align__(128) __half g_Kh[NXQ],  g_Kt[NXQ];
__device__ __align__(128) __half g_Vth[NXQ], g_Vtt[NXQ];
__device__ __align__(128) float  g_S[NS];
__device__ __align__(128) __half g_Ph[NS],   g_Pt[NS];

constexpr float C_SCALE = 64.0f;
constexpr float INV_C   = 1.0f / 64.0f;

// ---------------- helpers ----------------
__device__ __forceinline__ uint32_t smem_u32(const void* p) {
    uint32_t a;
    asm("{ .reg .u64 t; cvta.to.shared.u64 t, %1; cvt.u32.u64 %0, t; }"
        : "=r"(a) : "l"(p));
    return a;
}
__device__ __forceinline__ void cp16(uint32_t dst, const void* src) {
    asm volatile("cp.async.cg.shared.global [%0], [%1], 16;"
                 :: "r"(dst), "l"(src));
}
__device__ __forceinline__ void ldsm4(uint32_t* r, uint32_t a) {
    asm volatile("ldmatrix.sync.aligned.m8n8.x4.shared.b16 {%0,%1,%2,%3}, [%4];"
                 : "=r"(r[0]), "=r"(r[1]), "=r"(r[2]), "=r"(r[3]) : "r"(a));
}
__device__ __forceinline__ void mma16816(float* d, const uint32_t* a,
                                         const uint32_t* b) {
    asm volatile(
        "mma.sync.aligned.m16n8k16.row.col.f32.f16.f16.f32 "
        "{%0,%1,%2,%3}, {%4,%5,%6,%7}, {%8,%9}, {%0,%1,%2,%3};"
        : "+f"(d[0]), "+f"(d[1]), "+f"(d[2]), "+f"(d[3])
        : "r"(a[0]), "r"(a[1]), "r"(a[2]), "r"(a[3]), "r"(b[0]), "r"(b[1]));
}
// pack two fp32 -> fp16x2 (lo = first arg)
__device__ __forceinline__ uint32_t packh2(float lo, float hi) {
    uint32_t r;
    asm("cvt.rn.f16x2.f32 %0, %1, %2;" : "=r"(r) : "f"(hi), "f"(lo));
    return r;
}
// split scalar: h = fp16(v), t = fp16(h + c*(v-h))
__device__ __forceinline__ void split_ht(float v, float& hf, float& tf) {
    __half h = __float2half_rn(v);
    hf = __half2float(h);
    tf = fmaf(C_SCALE, v - hf, hf);
}

constexpr int TILE_MN = 128;
constexpr int STAGES  = 4;
constexpr int TSTRIDE = 40;                       // padded fp16 elems per row
constexpr int TILE_B  = TILE_MN * TSTRIDE * 2;    // 10240 B per array
constexpr int OFF_AH  = 0;
constexpr int OFF_AT  = TILE_B;
constexpr int OFF_BH  = 2 * TILE_B;
constexpr int OFF_BT  = 3 * TILE_B;
constexpr int STG_B   = 4 * TILE_B;               // 40960 B
constexpr int SMEM_B  = STAGES * STG_B;           // 163840 B

// ---------------- GEMM: C[M,N] = alpha * A[M,K] @ B[N,K]^T (+bias) ----------------
// Operands: (Ah,At),(Bh,Bt) fp16 scaled-residual pairs.
// OSPLIT=0: fp32 C. OSPLIT=1: fp16 pair out (Ch, Ct).
// bias_mode: 0 none, 1 per-column, 2 per-row.
template <int OSPLIT>
__global__ __launch_bounds__(256, 1)
void gemm_mma(const __half* __restrict__ Ah, const __half* __restrict__ At,
              const __half* __restrict__ Bh, const __half* __restrict__ Bt,
              const float* __restrict__ bias, int bias_mode,
              float* __restrict__ C,
              __half* __restrict__ Ch, __half* __restrict__ Ct,
              int M, int N, int K, float alpha,
              long long sA, long long sB, long long sC)
{
    extern __shared__ __align__(1024) char smem[];
    const uint32_t tb = smem_u32(smem);

    const int tid  = threadIdx.x;
    const int lane = tid & 31;
    const int wid  = tid >> 5;
    const int wm   = wid & 1;        // 2 warps along M (64 rows each)
    const int wn   = wid >> 1;       // 4 warps along N (32 cols each)

    const long long bm = (long long)blockIdx.y * TILE_MN;
    const long long bn = (long long)blockIdx.x * TILE_MN;
    Ah += (long long)blockIdx.z * sA + bm * K;
    At += (long long)blockIdx.z * sA + bm * K;
    Bh += (long long)blockIdx.z * sB + bn * K;
    Bt += (long long)blockIdx.z * sB + bn * K;

    const int ktot = K >> 5;

    // loader: 512 16B-chunks per array, 2 per thread
    auto load_tile = [&](int kt) {
        const int k0 = kt << 5;
        const uint32_t sbase = tb + (uint32_t)(kt % STAGES) * STG_B;
        #pragma unroll
        for (int rep = 0; rep < 2; ++rep) {
            const int ch  = tid + rep * 256;
            const int row = ch >> 2;
            const int c   = ch & 3;
            const size_t g = (size_t)row * K + k0 + c * 8;
            const uint32_t s = sbase + (uint32_t)(row * TSTRIDE + c * 8) * 2;
            cp16(s + OFF_AH, Ah + g);
            cp16(s + OFF_AT, At + g);
            cp16(s + OFF_BH, Bh + g);
            cp16(s + OFF_BT, Bt + g);
        }
    };

    // ldmatrix per-lane offsets (verified correct in earlier rounds)
    const int a_r = (lane & 7) + ((lane >> 3) & 1) * 8;
    const int a_k = (lane >> 4) * 8;
    const int b_n = (lane & 7) + ((lane >> 4) & 1) * 8;
    const int b_k = ((lane >> 3) & 1) * 8;

    float a1[4][4][4] = {};   // pass1: Ah.Bh
    float a2[4][4][4] = {};   // pass2: At.Bt

    #pragma unroll
    for (int s = 0; s < STAGES - 1; ++s) {
        load_tile(s);
        asm volatile("cp.async.commit_group;" ::: "memory");
    }

    #pragma unroll 1
    for (int kt = 0; kt < ktot; ++kt) {
        asm volatile("cp.async.wait_group %0;" :: "n"(STAGES - 2) : "memory");
        __syncthreads();

        if (kt + STAGES - 1 < ktot) load_tile(kt + STAGES - 1);
        asm volatile("cp.async.commit_group;" ::: "memory");

        const uint32_t s0 = tb + (uint32_t)(kt % STAGES) * STG_B;
        #pragma unroll
        for (int k16 = 0; k16 < 2; ++k16) {
            uint32_t aH[4][4], aT[4][4];
            #pragma unroll
            for (int mt = 0; mt < 4; ++mt) {
                const uint32_t off =
                    (uint32_t)((wm * 64 + mt * 16 + a_r) * TSTRIDE + k16 * 16 + a_k) * 2;
                ldsm4(aH[mt], s0 + OFF_AH + off);
                ldsm4(aT[mt], s0 + OFF_AT + off);
            }
            #pragma unroll
            for (int j = 0; j < 2; ++j) {
                uint32_t bH[4], bT[4];
                const uint32_t off =
                    (uint32_t)((wn * 32 + j * 16 + b_n) * TSTRIDE + k16 * 16 + b_k) * 2;
                ldsm4(bH, s0 + OFF_BH + off);
                ldsm4(bT, s0 + OFF_BT + off);
                #pragma unroll
                for (int mt = 0; mt < 4; ++mt) {
                    mma16816(a1[mt][2 * j],     aH[mt], bH);
                    mma16816(a1[mt][2 * j + 1], aH[mt], bH + 2);
                    mma16816(a2[mt][2 * j],     aT[mt], bT);
                    mma16816(a2[mt][2 * j + 1], aT[mt], bT + 2);
                }
            }
        }
    }

    // epilogue: v = a1 + (a2 - a1)/c
    const int gr = lane >> 2;
    const int c2 = (lane & 3) * 2;
    #pragma unroll
    for (int mt = 0; mt < 4; ++mt) {
        #pragma unroll
        for (int nt = 0; nt < 4; ++nt) {
            const long long m0 = bm + wm * 64 + mt * 16 + gr;
            const long long n  = bn + wn * 32 + nt * 8 + c2;
            const float* p1 = a1[mt][nt];
            const float* p2 = a2[mt][nt];
            float v[4];
            #pragma unroll
            for (int i = 0; i < 4; ++i)
                v[i] = (p1[i] + (p2[i] - p1[i]) * INV_C) * alpha;
            if (bias_mode == 1) {
                const float b0 = bias[n], b1 = bias[n + 1];
                v[0] += b0; v[1] += b1; v[2] += b0; v[3] += b1;
            } else if (bias_mode == 2) {
                const float b0 = bias[m0], b1 = bias[m0 + 8];
                v[0] += b0; v[1] += b0; v[2] += b1; v[3] += b1;
            }
            if (OSPLIT == 0) {
                float* Cb = C + (long long)blockIdx.z * sC;
                *(float2*)(Cb + m0 * N + n)       = make_float2(v[0], v[1]);
                *(float2*)(Cb + (m0 + 8) * N + n) = make_float2(v[2], v[3]);
            } else {
                __half* Hb = Ch + (long long)blockIdx.z * sC;
                __half* Tb = Ct + (long long)blockIdx.z * sC;
                float h0, t0, h1, t1;
                split_ht(v[0], h0, t0); split_ht(v[1], h1, t1);
                *(uint32_t*)(Hb + m0 * N + n) = packh2(h0, h1);
                *(uint32_t*)(Tb + m0 * N + n) = packh2(t0, t1);
                split_ht(v[2], h0, t0); split_ht(v[3], h1, t1);
                *(uint32_t*)(Hb + (m0 + 8) * N + n) = packh2(h0, h1);
                *(uint32_t*)(Tb + (m0 + 8) * N + n) = packh2(t0, t1);
            }
        }
    }
}

// ---------------- fp32 -> fp16 (h, t) split ----------------
__global__ __launch_bounds__(256)
void split2(const float4* __restrict__ in, uint2* __restrict__ hp,
            uint2* __restrict__ tp, int n4)
{
    int i = blockIdx.x * 256 + threadIdx.x;
    if (i >= n4) return;
    float4 v = in[i];
    float h0, t0, h1, t1, h2, t2, h3, t3;
    split_ht(v.x, h0, t0); split_ht(v.y, h1, t1);
    split_ht(v.z, h2, t2); split_ht(v.w, h3, t3);
    hp[i] = make_uint2(packh2(h0, h1), packh2(h2, h3));
    tp[i] = make_uint2(packh2(t0, t1), packh2(t2, t3));
}

// all three weight matrices in one launch (grid.y selects)
struct WArgs {
    const float4* in[3];
    uint2* hp[3];
    uint2* tp[3];
};
__global__ __launch_bounds__(256)
void splitW(WArgs a, int n4)
{
    const int w = blockIdx.y;
    int i = blockIdx.x * 256 + threadIdx.x;
    if (i >= n4) return;
    float4 v = a.in[w][i];
    float h0, t0, h1, t1, h2, t2, h3, t3;
    split_ht(v.x, h0, t0); split_ht(v.y, h1, t1);
    split_ht(v.z, h2, t2); split_ht(v.w, h3, t3);
    a.hp[w][i] = make_uint2(packh2(h0, h1), packh2(h2, h3));
    a.tp[w][i] = make_uint2(packh2(t0, t1), packh2(t2, t3));
}

// ---------------- softmax (fp32 in, fp16 h/t out) ----------------
__global__ __launch_bounds__(256)
void softmax_split(const float* __restrict__ S, __half* __restrict__ Ph,
                   __half* __restrict__ Pt)
{
    const long long row = blockIdx.x;
    const float* p = S + row * (long long)SKc;
    const int t = threadIdx.x;

    float v[8];
    float mx = -3.402823466e38f;
    #pragma unroll
    for (int i = 0; i < 8; i++) {
        v[i] = p[t + i * 256];
        mx = fmaxf(mx, v[i]);
    }
    __shared__ float shm[8], shs[8];
    #pragma unroll
    for (int o = 16; o > 0; o >>= 1)
        mx = fmaxf(mx, __shfl_xor_sync(0xffffffffu, mx, o));
    if ((t & 31) == 0) shm[t >> 5] = mx;
    __syncthreads();
    mx = shm[0];
    #pragma unroll
    for (int w = 1; w < 8; w++) mx = fmaxf(mx, shm[w]);

    float sum = 0.f;
    #pragma unroll
    for (int i = 0; i < 8; i++) { v[i] = expf(v[i] - mx); sum += v[i]; }
    #pragma unroll
    for (int o = 16; o > 0; o >>= 1)
        sum += __shfl_xor_sync(0xffffffffu, sum, o);
    if ((t & 31) == 0) shs[t >> 5] = sum;
    __syncthreads();
    float tot = 0.f;
    #pragma unroll
    for (int w = 0; w < 8; w++) tot += shs[w];

    const float inv = 1.0f / tot;
    __half* ph = Ph + row * (long long)SKc;
    __half* pt = Pt + row * (long long)SKc;
    #pragma unroll
    for (int i = 0; i < 8; i++) {
        const float pv = v[i] * inv;
        float hf, tf;
        split_ht(pv, hf, tf);
        ph[t + i * 256] = __float2half_rn(hf);
        pt[t + i * 256] = __float2half_rn(tf);
    }
}

// ---------------- launch ----------------
extern "C" void kernel_launch(void* const* d_in, const int* in_sizes, int n_in,
                              void* d_out, int out_size)
{
    const float* x   = (const float*)d_in[0];
    const float* ctx = (const float*)d_in[1];
    const float* Wq  = (const float*)d_in[2];
    const float* bq  = (const float*)d_in[3];
    const float* Wk  = (const float*)d_in[4];
    const float* bk  = (const float*)d_in[5];
    const float* Wv  = (const float*)d_in[6];
    const float* bv  = (const float*)d_in[7];
    float* out = (float*)d_out;

    __half *xh, *xt, *ch, *ct, *Wqh, *Wqt, *Wkh, *Wkt, *Wvh, *Wvt;
    __half *Qh, *Qt, *Kh, *Kt, *Vth, *Vtt, *Ph, *Pt;
    float* S;
    cudaGetSymbolAddress((void**)&xh,  g_xh);  cudaGetSymbolAddress((void**)&xt,  g_xt);
    cudaGetSymbolAddress((void**)&ch,  g_ch);  cudaGetSymbolAddress((void**)&ct,  g_ct);
    cudaGetSymbolAddress((void**)&Wqh, g_Wqh); cudaGetSymbolAddress((void**)&Wqt, g_Wqt);
    cudaGetSymbolAddress((void**)&Wkh, g_Wkh); cudaGetSymbolAddress((void**)&Wkt, g_Wkt);
    cudaGetSymbolAddress((void**)&Wvh, g_Wvh); cudaGetSymbolAddress((void**)&Wvt, g_Wvt);
    cudaGetSymbolAddress((void**)&Qh,  g_Qh);  cudaGetSymbolAddress((void**)&Qt,  g_Qt);
    cudaGetSymbolAddress((void**)&Kh,  g_Kh);  cudaGetSymbolAddress((void**)&Kt,  g_Kt);
    cudaGetSymbolAddress((void**)&Vth, g_Vth); cudaGetSymbolAddress((void**)&Vtt, g_Vtt);
    cudaGetSymbolAddress((void**)&Ph,  g_Ph);  cudaGetSymbolAddress((void**)&Pt,  g_Pt);
    cudaGetSymbolAddress((void**)&S,   g_S);

    cudaFuncSetAttribute(gemm_mma<0>, cudaFuncAttributeMaxDynamicSharedMemorySize, SMEM_B);
    cudaFuncSetAttribute(gemm_mma<1>, cudaFuncAttributeMaxDynamicSharedMemorySize, SMEM_B);

    const int n4x = (int)(NXQ / 4), n4w = DIMc * DIMc / 4;

    // launches ordered so ncu (-s 5 -c 1, after 1 correctness call... window
    // lands on launch #6 of the timed sequence) captures the S GEMM.
    split2<<<(n4x + 255) / 256, 256>>>((const float4*)x,   (uint2*)xh, (uint2*)xt, n4x);   // 1
    split2<<<(n4x + 255) / 256, 256>>>((const float4*)ctx, (uint2*)ch, (uint2*)ct, n4x);   // 2
    WArgs wa;
    wa.in[0] = (const float4*)Wq; wa.hp[0] = (uint2*)Wqh; wa.tp[0] = (uint2*)Wqt;
    wa.in[1] = (const float4*)Wk; wa.hp[1] = (uint2*)Wkh; wa.tp[1] = (uint2*)Wkt;
    wa.in[2] = (const float4*)Wv; wa.hp[2] = (uint2*)Wvh; wa.tp[2] = (uint2*)Wvt;
    splitW<<<dim3((n4w + 255) / 256, 3), 256>>>(wa, n4w);                                  // 3

    const float scale = 0.03125f;   // 1/sqrt(1024)

    // 4: Q = x @ Wq^T + bq -> split
    gemm_mma<1><<<dim3(DIMc / 128, (NB * SQc) / 128, 1), 256, SMEM_B>>>(
        xh, xt, Wqh, Wqt, bq, 1, nullptr, Qh, Qt,
        NB * SQc, DIMc, DIMc, 1.f, 0, 0, 0);
    // 5: K = ctx @ Wk^T + bk -> split
    gemm_mma<1><<<dim3(DIMc / 128, (NB * SKc) / 128, 1), 256, SMEM_B>>>(
        ch, ct, Wkh, Wkt, bk, 1, nullptr, Kh, Kt,
        NB * SKc, DIMc, DIMc, 1.f, 0, 0, 0);
    // 6: S = (Q @ K^T)/32  (fp32)   per batch [2048, 2048]   <- ncu window
    gemm_mma<0><<<dim3(SKc / 128, SQc / 128, NB), 256, SMEM_B>>>(
        Qh, Qt, Kh, Kt, nullptr, 0, S, nullptr, nullptr,
        SQc, SKc, DIMc, scale,
        (long long)SQc * DIMc, (long long)SKc * DIMc, (long long)SQc * SKc);
    // 7: Vt = Wv @ ctx^T + bv(row) -> split   per batch [1024, 2048]
    gemm_mma<1><<<dim3(SKc / 128, DIMc / 128, NB), 256, SMEM_B>>>(
        Wvh, Wvt, ch, ct, bv, 2, nullptr, Vth, Vtt,
        DIMc, SKc, DIMc, 1.f, 0, (long long)SKc * DIMc, (long long)DIMc * SKc);
    // 8: softmax -> split P
    softmax_split<<<NB * SQc, 256>>>(S, Ph, Pt);
    // 9: O = P @ Vt^T (fp32)        per batch [2048, 1024]
    gemm_mma<0><<<dim3(DIMc / 128, SQc / 128, NB), 256, SMEM_B>>>(
        Ph, Pt, Vth, Vtt, nullptr, 0, out, nullptr, nullptr,
        SQc, DIMc, SKc, 1.f,
        (long long)SQc * SKc, (long long)DIMc * SKc, (long long)SQc * DIMc);
}

// round 9
// speedup vs baseline: 1.2215x; 1.0305x over previous
#include <cuda_runtime.h>
#include <cuda_fp16.h>
#include <cstdint>

// CrossAttention B=8, SQ=SK=2048, DIM=1024, fp32 in/out.
// GEMMs: mma.sync m16n8k16 fp16, Ootomo scaled-residual 2-pass.
//   pass1 (main):       fp32 accumulator
//   pass2 (correction): fp16 accumulator (halves acc regs -> 64x64 warptile)
// result = acc1 + (acc2 - acc1)/64
// CTA tile 256x128, warp grid 4x2, warptile 64x64, 3-stage cp.async.

#define DIMc 1024
#define NB   8
#define SQc  2048
#define SKc  2048

#define NXQ ((size_t)NB * SQc * DIMc)   // 16.7M
#define NS  ((size_t)NB * SQc * SKc)    // 33.5M

__device__ __align__(128) __half g_xh[NXQ],  g_xt[NXQ];
__device__ __align__(128) __half g_ch[NXQ],  g_ct[NXQ];
__device__ __align__(128) __half g_Wqh[DIMc*DIMc], g_Wqt[DIMc*DIMc];
__device__ __align__(128) __half g_Wkh[DIMc*DIMc], g_Wkt[DIMc*DIMc];
__device__ __align__(128) __half g_Wvh[DIMc*DIMc], g_Wvt[DIMc*DIMc];
__device__ __align__(128) __half g_Qh[NXQ],  g_Qt[NXQ];
__device__ __align__(128) __half g_Kh[NXQ],  g_Kt[NXQ];
__device__ __align__(128) __half g_Vth[NXQ], g_Vtt[NXQ];
__device__ __align__(128) float  g_S[NS];
__device__ __align__(128) __half g_Ph[NS],   g_Pt[NS];

constexpr float C_SCALE = 64.0f;
constexpr float INV_C   = 1.0f / 64.0f;

// ---------------- helpers ----------------
__device__ __forceinline__ uint32_t smem_u32(const void* p) {
    uint32_t a;
    asm("{ .reg .u64 t; cvta.to.shared.u64 t, %1; cvt.u32.u64 %0, t; }"
        : "=r"(a) : "l"(p));
    return a;
}
__device__ __forceinline__ void cp16(uint32_t dst, const void* src) {
    asm volatile("cp.async.cg.shared.global [%0], [%1], 16;"
                 :: "r"(dst), "l"(src));
}
__device__ __forceinline__ void ldsm4(uint32_t* r, uint32_t a) {
    asm volatile("ldmatrix.sync.aligned.m8n8.x4.shared.b16 {%0,%1,%2,%3}, [%4];"
                 : "=r"(r[0]), "=r"(r[1]), "=r"(r[2]), "=r"(r[3]) : "r"(a));
}
__device__ __forceinline__ void mma_f32(float* d, const uint32_t* a,
                                        const uint32_t* b) {
    asm volatile(
        "mma.sync.aligned.m16n8k16.row.col.f32.f16.f16.f32 "
        "{%0,%1,%2,%3}, {%4,%5,%6,%7}, {%8,%9}, {%0,%1,%2,%3};"
        : "+f"(d[0]), "+f"(d[1]), "+f"(d[2]), "+f"(d[3])
        : "r"(a[0]), "r"(a[1]), "r"(a[2]), "r"(a[3]), "r"(b[0]), "r"(b[1]));
}
__device__ __forceinline__ void mma_f16(uint32_t* d, const uint32_t* a,
                                        const uint32_t* b) {
    asm volatile(
        "mma.sync.aligned.m16n8k16.row.col.f16.f16.f16.f16 "
        "{%0,%1}, {%2,%3,%4,%5}, {%6,%7}, {%0,%1};"
        : "+r"(d[0]), "+r"(d[1])
        : "r"(a[0]), "r"(a[1]), "r"(a[2]), "r"(a[3]), "r"(b[0]), "r"(b[1]));
}
// pack two fp32 -> fp16x2 (lo = first arg)
__device__ __forceinline__ uint32_t packh2(float lo, float hi) {
    uint32_t r;
    asm("cvt.rn.f16x2.f32 %0, %1, %2;" : "=r"(r) : "f"(hi), "f"(lo));
    return r;
}
// split scalar: h = fp16(v), t = fp16(h + c*(v-h))
__device__ __forceinline__ void split_ht(float v, float& hf, float& tf) {
    __half h = __float2half_rn(v);
    hf = __half2float(h);
    tf = fmaf(C_SCALE, v - hf, hf);
}

constexpr int TILE_M  = 256;
constexpr int TILE_N  = 128;
constexpr int STAGES  = 3;
constexpr int TSTRIDE = 40;                        // padded fp16 elems per row
constexpr int A_ARR_B = TILE_M * TSTRIDE * 2;      // 20480 B per A array
constexpr int B_ARR_B = TILE_N * TSTRIDE * 2;      // 10240 B per B array
constexpr int OFF_AH  = 0;
constexpr int OFF_AT  = A_ARR_B;
constexpr int OFF_BH  = 2 * A_ARR_B;
constexpr int OFF_BT  = 2 * A_ARR_B + B_ARR_B;
constexpr int STG_B   = 2 * A_ARR_B + 2 * B_ARR_B; // 61440 B
constexpr int SMEM_B  = STAGES * STG_B;            // 184320 B

// ---------------- GEMM: C[M,N] = alpha * A[M,K] @ B[N,K]^T (+bias) ----------------
// Operands: (Ah,At),(Bh,Bt) fp16 scaled-residual pairs.
// OSPLIT=0: fp32 C. OSPLIT=1: fp16 pair out (Ch, Ct).
// bias_mode: 0 none, 1 per-column, 2 per-row.
template <int OSPLIT>
__global__ __launch_bounds__(256, 1)
void gemm_mma(const __half* __restrict__ Ah, const __half* __restrict__ At,
              const __half* __restrict__ Bh, const __half* __restrict__ Bt,
              const float* __restrict__ bias, int bias_mode,
              float* __restrict__ C,
              __half* __restrict__ Ch, __half* __restrict__ Ct,
              int M, int N, int K, float alpha,
              long long sA, long long sB, long long sC)
{
    extern __shared__ __align__(1024) char smem[];
    const uint32_t tb = smem_u32(smem);

    const int tid  = threadIdx.x;
    const int lane = tid & 31;
    const int wid  = tid >> 5;
    const int wm   = wid & 3;        // 4 warps along M (64 rows each)
    const int wn   = wid >> 2;       // 2 warps along N (64 cols each)

    const long long bm = (long long)blockIdx.y * TILE_M;
    const long long bn = (long long)blockIdx.x * TILE_N;
    Ah += (long long)blockIdx.z * sA + bm * K;
    At += (long long)blockIdx.z * sA + bm * K;
    Bh += (long long)blockIdx.z * sB + bn * K;
    Bt += (long long)blockIdx.z * sB + bn * K;

    const int ktot = K >> 5;

    // loader: A 1024 chunks/array (4/thread), B 512 (2/thread)
    auto load_tile = [&](int kt) {
        const int k0 = kt << 5;
        const uint32_t sbase = tb + (uint32_t)(kt % STAGES) * STG_B;
        #pragma unroll
        for (int rep = 0; rep < 4; ++rep) {
            const int ch  = tid + rep * 256;
            const int row = ch >> 2;
            const int c   = ch & 3;
            const size_t g = (size_t)row * K + k0 + c * 8;
            const uint32_t s = sbase + (uint32_t)(row * TSTRIDE + c * 8) * 2;
            cp16(s + OFF_AH, Ah + g);
            cp16(s + OFF_AT, At + g);
        }
        #pragma unroll
        for (int rep = 0; rep < 2; ++rep) {
            const int ch  = tid + rep * 256;
            const int row = ch >> 2;
            const int c   = ch & 3;
            const size_t g = (size_t)row * K + k0 + c * 8;
            const uint32_t s = sbase + (uint32_t)(row * TSTRIDE + c * 8) * 2;
            cp16(s + OFF_BH, Bh + g);
            cp16(s + OFF_BT, Bt + g);
        }
    };

    // ldmatrix per-lane offsets (layout verified in earlier rounds)
    const int a_r = (lane & 7) + ((lane >> 3) & 1) * 8;
    const int a_k = (lane >> 4) * 8;
    const int b_n = (lane & 7) + ((lane >> 4) & 1) * 8;
    const int b_k = ((lane >> 3) & 1) * 8;

    float    a1[4][8][4] = {};   // pass1: Ah.Bh   (fp32 acc)
    uint32_t a2[4][8][2] = {};   // pass2: At.Bt   (fp16 acc, packed)

    #pragma unroll
    for (int s = 0; s < STAGES - 1; ++s) {
        load_tile(s);
        asm volatile("cp.async.commit_group;" ::: "memory");
    }

    #pragma unroll 1
    for (int kt = 0; kt < ktot; ++kt) {
        asm volatile("cp.async.wait_group %0;" :: "n"(STAGES - 2) : "memory");
        __syncthreads();

        if (kt + STAGES - 1 < ktot) load_tile(kt + STAGES - 1);
        asm volatile("cp.async.commit_group;" ::: "memory");

        const uint32_t s0 = tb + (uint32_t)(kt % STAGES) * STG_B;
        #pragma unroll
        for (int k16 = 0; k16 < 2; ++k16) {
            uint32_t aH[4][4], aT[4][4];
            #pragma unroll
            for (int mt = 0; mt < 4; ++mt) {
                const uint32_t off =
                    (uint32_t)((wm * 64 + mt * 16 + a_r) * TSTRIDE + k16 * 16 + a_k) * 2;
                ldsm4(aH[mt], s0 + OFF_AH + off);
                ldsm4(aT[mt], s0 + OFF_AT + off);
            }
            #pragma unroll
            for (int j = 0; j < 4; ++j) {
                uint32_t bH[4], bT[4];
                const uint32_t off =
                    (uint32_t)((wn * 64 + j * 16 + b_n) * TSTRIDE + k16 * 16 + b_k) * 2;
                ldsm4(bH, s0 + OFF_BH + off);
                ldsm4(bT, s0 + OFF_BT + off);
                #pragma unroll
                for (int mt = 0; mt < 4; ++mt) {
                    mma_f32(a1[mt][2 * j],     aH[mt], bH);
                    mma_f32(a1[mt][2 * j + 1], aH[mt], bH + 2);
                    mma_f16(a2[mt][2 * j],     aT[mt], bT);
                    mma_f16(a2[mt][2 * j + 1], aT[mt], bT + 2);
                }
            }
        }
    }

    // epilogue: v = a1 + (a2 - a1)/c
    const int gr = lane >> 2;
    const int c2 = (lane & 3) * 2;
    #pragma unroll
    for (int mt = 0; mt < 4; ++mt) {
        #pragma unroll
        for (int nt = 0; nt < 8; ++nt) {
            const long long m0 = bm + wm * 64 + mt * 16 + gr;
            const long long n  = bn + wn * 64 + nt * 8 + c2;
            const float* p1 = a1[mt][nt];
            float2 q0 = __half22float2(
                *reinterpret_cast<const __half2*>(&a2[mt][nt][0]));
            float2 q1 = __half22float2(
                *reinterpret_cast<const __half2*>(&a2[mt][nt][1]));
            float v[4];
            v[0] = (p1[0] + (q0.x - p1[0]) * INV_C) * alpha;
            v[1] = (p1[1] + (q0.y - p1[1]) * INV_C) * alpha;
            v[2] = (p1[2] + (q1.x - p1[2]) * INV_C) * alpha;
            v[3] = (p1[3] + (q1.y - p1[3]) * INV_C) * alpha;
            if (bias_mode == 1) {
                const float b0 = bias[n], b1 = bias[n + 1];
                v[0] += b0; v[1] += b1; v[2] += b0; v[3] += b1;
            } else if (bias_mode == 2) {
                const float b0 = bias[m0], b1 = bias[m0 + 8];
                v[0] += b0; v[1] += b0; v[2] += b1; v[3] += b1;
            }
            if (OSPLIT == 0) {
                float* Cb = C + (long long)blockIdx.z * sC;
                *(float2*)(Cb + m0 * N + n)       = make_float2(v[0], v[1]);
                *(float2*)(Cb + (m0 + 8) * N + n) = make_float2(v[2], v[3]);
            } else {
                __half* Hb = Ch + (long long)blockIdx.z * sC;
                __half* Tb = Ct + (long long)blockIdx.z * sC;
                float h0, t0, h1, t1;
                split_ht(v[0], h0, t0); split_ht(v[1], h1, t1);
                *(uint32_t*)(Hb + m0 * N + n) = packh2(h0, h1);
                *(uint32_t*)(Tb + m0 * N + n) = packh2(t0, t1);
                split_ht(v[2], h0, t0); split_ht(v[3], h1, t1);
                *(uint32_t*)(Hb + (m0 + 8) * N + n) = packh2(h0, h1);
                *(uint32_t*)(Tb + (m0 + 8) * N + n) = packh2(t0, t1);
            }
        }
    }
}

// ---------------- fp32 -> fp16 (h, t) split ----------------
__global__ __launch_bounds__(256)
void split2(const float4* __restrict__ in, uint2* __restrict__ hp,
            uint2* __restrict__ tp, int n4)
{
    int i = blockIdx.x * 256 + threadIdx.x;
    if (i >= n4) return;
    float4 v = in[i];
    float h0, t0, h1, t1, h2, t2, h3, t3;
    split_ht(v.x, h0, t0); split_ht(v.y, h1, t1);
    split_ht(v.z, h2, t2); split_ht(v.w, h3, t3);
    hp[i] = make_uint2(packh2(h0, h1), packh2(h2, h3));
    tp[i] = make_uint2(packh2(t0, t1), packh2(t2, t3));
}

struct WArgs {
    const float4* in[3];
    uint2* hp[3];
    uint2* tp[3];
};
__global__ __launch_bounds__(256)
void splitW(WArgs a, int n4)
{
    const int w = blockIdx.y;
    int i = blockIdx.x * 256 + threadIdx.x;
    if (i >= n4) return;
    float4 v = a.in[w][i];
    float h0, t0, h1, t1, h2, t2, h3, t3;
    split_ht(v.x, h0, t0); split_ht(v.y, h1, t1);
    split_ht(v.z, h2, t2); split_ht(v.w, h3, t3);
    a.hp[w][i] = make_uint2(packh2(h0, h1), packh2(h2, h3));
    a.tp[w][i] = make_uint2(packh2(t0, t1), packh2(t2, t3));
}

// ---------------- softmax (fp32 in, fp16 h/t out) ----------------
__global__ __launch_bounds__(256)
void softmax_split(const float* __restrict__ S, __half* __restrict__ Ph,
                   __half* __restrict__ Pt)
{
    const long long row = blockIdx.x;
    const float* p = S + row * (long long)SKc;
    const int t = threadIdx.x;

    float v[8];
    float mx = -3.402823466e38f;
    #pragma unroll
    for (int i = 0; i < 8; i++) {
        v[i] = p[t + i * 256];
        mx = fmaxf(mx, v[i]);
    }
    __shared__ float shm[8], shs[8];
    #pragma unroll
    for (int o = 16; o > 0; o >>= 1)
        mx = fmaxf(mx, __shfl_xor_sync(0xffffffffu, mx, o));
    if ((t & 31) == 0) shm[t >> 5] = mx;
    __syncthreads();
    mx = shm[0];
    #pragma unroll
    for (int w = 1; w < 8; w++) mx = fmaxf(mx, shm[w]);

    float sum = 0.f;
    #pragma unroll
    for (int i = 0; i < 8; i++) { v[i] = expf(v[i] - mx); sum += v[i]; }
    #pragma unroll
    for (int o = 16; o > 0; o >>= 1)
        sum += __shfl_xor_sync(0xffffffffu, sum, o);
    if ((t & 31) == 0) shs[t >> 5] = sum;
    __syncthreads();
    float tot = 0.f;
    #pragma unroll
    for (int w = 0; w < 8; w++) tot += shs[w];

    const float inv = 1.0f / tot;
    __half* ph = Ph + row * (long long)SKc;
    __half* pt = Pt + row * (long long)SKc;
    #pragma unroll
    for (int i = 0; i < 8; i++) {
        const float pv = v[i] * inv;
        float hf, tf;
        split_ht(pv, hf, tf);
        ph[t + i * 256] = __float2half_rn(hf);
        pt[t + i * 256] = __float2half_rn(tf);
    }
}

// ---------------- launch ----------------
extern "C" void kernel_launch(void* const* d_in, const int* in_sizes, int n_in,
                              void* d_out, int out_size)
{
    const float* x   = (const float*)d_in[0];
    const float* ctx = (const float*)d_in[1];
    const float* Wq  = (const float*)d_in[2];
    const float* bq  = (const float*)d_in[3];
    const float* Wk  = (const float*)d_in[4];
    const float* bk  = (const float*)d_in[5];
    const float* Wv  = (const float*)d_in[6];
    const float* bv  = (const float*)d_in[7];
    float* out = (float*)d_out;

    __half *xh, *xt, *ch, *ct, *Wqh, *Wqt, *Wkh, *Wkt, *Wvh, *Wvt;
    __half *Qh, *Qt, *Kh, *Kt, *Vth, *Vtt, *Ph, *Pt;
    float* S;
    cudaGetSymbolAddress((void**)&xh,  g_xh);  cudaGetSymbolAddress((void**)&xt,  g_xt);
    cudaGetSymbolAddress((void**)&ch,  g_ch);  cudaGetSymbolAddress((void**)&ct,  g_ct);
    cudaGetSymbolAddress((void**)&Wqh, g_Wqh); cudaGetSymbolAddress((void**)&Wqt, g_Wqt);
    cudaGetSymbolAddress((void**)&Wkh, g_Wkh); cudaGetSymbolAddress((void**)&Wkt, g_Wkt);
    cudaGetSymbolAddress((void**)&Wvh, g_Wvh); cudaGetSymbolAddress((void**)&Wvt, g_Wvt);
    cudaGetSymbolAddress((void**)&Qh,  g_Qh);  cudaGetSymbolAddress((void**)&Qt,  g_Qt);
    cudaGetSymbolAddress((void**)&Kh,  g_Kh);  cudaGetSymbolAddress((void**)&Kt,  g_Kt);
    cudaGetSymbolAddress((void**)&Vth, g_Vth); cudaGetSymbolAddress((void**)&Vtt, g_Vtt);
    cudaGetSymbolAddress((void**)&Ph,  g_Ph);  cudaGetSymbolAddress((void**)&Pt,  g_Pt);
    cudaGetSymbolAddress((void**)&S,   g_S);

    cudaFuncSetAttribute(gemm_mma<0>, cudaFuncAttributeMaxDynamicSharedMemorySize, SMEM_B);
    cudaFuncSetAttribute(gemm_mma<1>, cudaFuncAttributeMaxDynamicSharedMemorySize, SMEM_B);

    const int n4x = (int)(NXQ / 4), n4w = DIMc * DIMc / 4;

    split2<<<(n4x + 255) / 256, 256>>>((const float4*)x,   (uint2*)xh, (uint2*)xt, n4x);   // 1
    split2<<<(n4x + 255) / 256, 256>>>((const float4*)ctx, (uint2*)ch, (uint2*)ct, n4x);   // 2
    WArgs wa;
    wa.in[0] = (const float4*)Wq; wa.hp[0] = (uint2*)Wqh; wa.tp[0] = (uint2*)Wqt;
    wa.in[1] = (const float4*)Wk; wa.hp[1] = (uint2*)Wkh; wa.tp[1] = (uint2*)Wkt;
    wa.in[2] = (const float4*)Wv; wa.hp[2] = (uint2*)Wvh; wa.tp[2] = (uint2*)Wvt;
    splitW<<<dim3((n4w + 255) / 256, 3), 256>>>(wa, n4w);                                  // 3

    const float scale = 0.03125f;   // 1/sqrt(1024)

    // 4: Q = x @ Wq^T + bq -> split
    gemm_mma<1><<<dim3(DIMc / TILE_N, (NB * SQc) / TILE_M, 1), 256, SMEM_B>>>(
        xh, xt, Wqh, Wqt, bq, 1, nullptr, Qh, Qt,
        NB * SQc, DIMc, DIMc, 1.f, 0, 0, 0);
    // 5: K = ctx @ Wk^T + bk -> split
    gemm_mma<1><<<dim3(DIMc / TILE_N, (NB * SKc) / TILE_M, 1), 256, SMEM_B>>>(
        ch, ct, Wkh, Wkt, bk, 1, nullptr, Kh, Kt,
        NB * SKc, DIMc, DIMc, 1.f, 0, 0, 0);
    // 6: S = (Q @ K^T)/32  (fp32)   per batch [2048, 2048]   <- ncu window
    gemm_mma<0><<<dim3(SKc / TILE_N, SQc / TILE_M, NB), 256, SMEM_B>>>(
        Qh, Qt, Kh, Kt, nullptr, 0, S, nullptr, nullptr,
        SQc, SKc, DIMc, scale,
        (long long)SQc * DIMc, (long long)SKc * DIMc, (long long)SQc * SKc);
    // 7: Vt = Wv @ ctx^T + bv(row) -> split   per batch [1024, 2048]
    gemm_mma<1><<<dim3(SKc / TILE_N, DIMc / TILE_M, NB), 256, SMEM_B>>>(
        Wvh, Wvt, ch, ct, bv, 2, nullptr, Vth, Vtt,
        DIMc, SKc, DIMc, 1.f, 0, (long long)SKc * DIMc, (long long)DIMc * SKc);
    // 8: softmax -> split P
    softmax_split<<<NB * SQc, 256>>>(S, Ph, Pt);
    // 9: O = P @ Vt^T (fp32)        per batch [2048, 1024]
    gemm_mma<0><<<dim3(DIMc / TILE_N, SQc / TILE_M, NB), 256, SMEM_B>>>(
        Ph, Pt, Vth, Vtt, nullptr, 0, out, nullptr, nullptr,
        SQc, DIMc, SKc, 1.f,
        (long long)SQc * SKc, (long long)DIMc * SKc, (long long)SQc * DIMc);
}

// round 11
// speedup vs baseline: 1.7226x; 1.4103x over previous
#include <cuda_runtime.h>
#include <cuda_fp16.h>
#include <cstdint>

// CrossAttention B=8, SQ=SK=2048, DIM=1024, fp32 in/out.
// Projections (Q,K,Vt): Ootomo 2-pass fp16 (fp32 main acc + fp16 corr acc),
//   output rounded to a single fp16 array.
// Attention (S = QK^T/32, O = P.Vt^T): single-pass fp16 mma, fp32 accum
//   (products exact; error = input quantization only, ~3e-4).

#define DIMc 1024
#define NB   8
#define SQc  2048
#define SKc  2048

#define NXQ ((size_t)NB * SQc * DIMc)   // 16.7M
#define NS  ((size_t)NB * SQc * SKc)    // 33.5M

__device__ __align__(128) __half g_xh[NXQ],  g_xt[NXQ];
__device__ __align__(128) __half g_ch[NXQ],  g_ct[NXQ];
__device__ __align__(128) __half g_Wqh[DIMc*DIMc], g_Wqt[DIMc*DIMc];
__device__ __align__(128) __half g_Wkh[DIMc*DIMc], g_Wkt[DIMc*DIMc];
__device__ __align__(128) __half g_Wvh[DIMc*DIMc], g_Wvt[DIMc*DIMc];
__device__ __align__(128) __half g_Q[NXQ];
__device__ __align__(128) __half g_K[NXQ];
__device__ __align__(128) __half g_Vt[NXQ];
__device__ __align__(128) float  g_S[NS];
__device__ __align__(128) __half g_P[NS];

constexpr float C_SCALE = 64.0f;
constexpr float INV_C   = 1.0f / 64.0f;

// ---------------- helpers ----------------
__device__ __forceinline__ uint32_t smem_u32(const void* p) {
    uint32_t a;
    asm("{ .reg .u64 t; cvta.to.shared.u64 t, %1; cvt.u32.u64 %0, t; }"
        : "=r"(a) : "l"(p));
    return a;
}
__device__ __forceinline__ void cp16(uint32_t dst, const void* src) {
    asm volatile("cp.async.cg.shared.global [%0], [%1], 16;"
                 :: "r"(dst), "l"(src));
}
__device__ __forceinline__ void ldsm4(uint32_t* r, uint32_t a) {
    asm volatile("ldmatrix.sync.aligned.m8n8.x4.shared.b16 {%0,%1,%2,%3}, [%4];"
                 : "=r"(r[0]), "=r"(r[1]), "=r"(r[2]), "=r"(r[3]) : "r"(a));
}
__device__ __forceinline__ void mma_f32(float* d, const uint32_t* a,
                                        const uint32_t* b) {
    asm volatile(
        "mma.sync.aligned.m16n8k16.row.col.f32.f16.f16.f32 "
        "{%0,%1,%2,%3}, {%4,%5,%6,%7}, {%8,%9}, {%0,%1,%2,%3};"
        : "+f"(d[0]), "+f"(d[1]), "+f"(d[2]), "+f"(d[3])
        : "r"(a[0]), "r"(a[1]), "r"(a[2]), "r"(a[3]), "r"(b[0]), "r"(b[1]));
}
__device__ __forceinline__ void mma_f16(uint32_t* d, const uint32_t* a,
                                        const uint32_t* b) {
    asm volatile(
        "mma.sync.aligned.m16n8k16.row.col.f16.f16.f16.f16 "
        "{%0,%1}, {%2,%3,%4,%5}, {%6,%7}, {%0,%1};"
        : "+r"(d[0]), "+r"(d[1])
        : "r"(a[0]), "r"(a[1]), "r"(a[2]), "r"(a[3]), "r"(b[0]), "r"(b[1]));
}
__device__ __forceinline__ uint32_t packh2(float lo, float hi) {
    uint32_t r;
    asm("cvt.rn.f16x2.f32 %0, %1, %2;" : "=r"(r) : "f"(hi), "f"(lo));
    return r;
}
// split scalar: h = fp16(v), t = fp16(h + c*(v-h))
__device__ __forceinline__ void split_ht(float v, float& hf, float& tf) {
    __half h = __float2half_rn(v);
    hf = __half2float(h);
    tf = fmaf(C_SCALE, v - hf, hf);
}

constexpr int TILE_M  = 256;
constexpr int TILE_N  = 128;
constexpr int TSTRIDE = 40;                        // padded fp16 elems per row
constexpr int A_ARR_B = TILE_M * TSTRIDE * 2;      // 20480 B
constexpr int B_ARR_B = TILE_N * TSTRIDE * 2;      // 10240 B

// ---- 2-pass kernel layout (4 arrays, 3 stages) ----
constexpr int STAGES2 = 3;
constexpr int OFF_AH2 = 0;
constexpr int OFF_AT2 = A_ARR_B;
constexpr int OFF_BH2 = 2 * A_ARR_B;
constexpr int OFF_BT2 = 2 * A_ARR_B + B_ARR_B;
constexpr int STG_B2  = 2 * A_ARR_B + 2 * B_ARR_B; // 61440
constexpr int SMEM_B2 = STAGES2 * STG_B2;          // 184320

// ---- 1-pass kernel layout (2 arrays, 4 stages) ----
constexpr int STAGES1 = 4;
constexpr int OFF_AH1 = 0;
constexpr int OFF_BH1 = A_ARR_B;
constexpr int STG_B1  = A_ARR_B + B_ARR_B;         // 30720
constexpr int SMEM_B1 = STAGES1 * STG_B1;          // 122880

// =============== 2-pass GEMM: Ch = fp16( A@B^T + bias ) ===============
// bias_mode: 1 per-column, 2 per-row.
__global__ __launch_bounds__(256, 1)
void gemm_mma2(const __half* __restrict__ Ah, const __half* __restrict__ At,
               const __half* __restrict__ Bh, const __half* __restrict__ Bt,
               const float* __restrict__ bias, int bias_mode,
               __half* __restrict__ Ch,
               int M, int N, int K,
               long long sA, long long sB, long long sC)
{
    extern __shared__ __align__(1024) char smem[];
    const uint32_t tb = smem_u32(smem);

    const int tid  = threadIdx.x;
    const int lane = tid & 31;
    const int wid  = tid >> 5;
    const int wm   = wid & 3;
    const int wn   = wid >> 2;

    const long long bm = (long long)blockIdx.y * TILE_M;
    const long long bn = (long long)blockIdx.x * TILE_N;
    Ah += (long long)blockIdx.z * sA + bm * K;
    At += (long long)blockIdx.z * sA + bm * K;
    Bh += (long long)blockIdx.z * sB + bn * K;
    Bt += (long long)blockIdx.z * sB + bn * K;

    const int ktot = K >> 5;

    auto load_tile = [&](int kt) {
        const int k0 = kt << 5;
        const uint32_t sbase = tb + (uint32_t)(kt % STAGES2) * STG_B2;
        #pragma unroll
        for (int rep = 0; rep < 4; ++rep) {
            const int ch  = tid + rep * 256;
            const int row = ch >> 2;
            const int c   = ch & 3;
            const size_t g = (size_t)row * K + k0 + c * 8;
            const uint32_t s = sbase + (uint32_t)(row * TSTRIDE + c * 8) * 2;
            cp16(s + OFF_AH2, Ah + g);
            cp16(s + OFF_AT2, At + g);
        }
        #pragma unroll
        for (int rep = 0; rep < 2; ++rep) {
            const int ch  = tid + rep * 256;
            const int row = ch >> 2;
            const int c   = ch & 3;
            const size_t g = (size_t)row * K + k0 + c * 8;
            const uint32_t s = sbase + (uint32_t)(row * TSTRIDE + c * 8) * 2;
            cp16(s + OFF_BH2, Bh + g);
            cp16(s + OFF_BT2, Bt + g);
        }
    };

    const int a_r = (lane & 7) + ((lane >> 3) & 1) * 8;
    const int a_k = (lane >> 4) * 8;
    const int b_n = (lane & 7) + ((lane >> 4) & 1) * 8;
    const int b_k = ((lane >> 3) & 1) * 8;

    float    a1[4][8][4] = {};
    uint32_t a2[4][8][2] = {};

    #pragma unroll
    for (int s = 0; s < STAGES2 - 1; ++s) {
        load_tile(s);
        asm volatile("cp.async.commit_group;" ::: "memory");
    }

    #pragma unroll 1
    for (int kt = 0; kt < ktot; ++kt) {
        asm volatile("cp.async.wait_group %0;" :: "n"(STAGES2 - 2) : "memory");
        __syncthreads();

        if (kt + STAGES2 - 1 < ktot) load_tile(kt + STAGES2 - 1);
        asm volatile("cp.async.commit_group;" ::: "memory");

        const uint32_t s0 = tb + (uint32_t)(kt % STAGES2) * STG_B2;
        #pragma unroll
        for (int k16 = 0; k16 < 2; ++k16) {
            uint32_t aH[4][4], aT[4][4];
            #pragma unroll
            for (int mt = 0; mt < 4; ++mt) {
                const uint32_t off =
                    (uint32_t)((wm * 64 + mt * 16 + a_r) * TSTRIDE + k16 * 16 + a_k) * 2;
                ldsm4(aH[mt], s0 + OFF_AH2 + off);
                ldsm4(aT[mt], s0 + OFF_AT2 + off);
            }
            #pragma unroll
            for (int j = 0; j < 4; ++j) {
                uint32_t bH[4], bT[4];
                const uint32_t off =
                    (uint32_t)((wn * 64 + j * 16 + b_n) * TSTRIDE + k16 * 16 + b_k) * 2;
                ldsm4(bH, s0 + OFF_BH2 + off);
                ldsm4(bT, s0 + OFF_BT2 + off);
                #pragma unroll
                for (int mt = 0; mt < 4; ++mt) {
                    mma_f32(a1[mt][2 * j],     aH[mt], bH);
                    mma_f32(a1[mt][2 * j + 1], aH[mt], bH + 2);
                    mma_f16(a2[mt][2 * j],     aT[mt], bT);
                    mma_f16(a2[mt][2 * j + 1], aT[mt], bT + 2);
                }
            }
        }
    }

    // epilogue: v = a1 + (a2 - a1)/c + bias, round to fp16
    const int gr = lane >> 2;
    const int c2 = (lane & 3) * 2;
    __half* Cb = Ch + (long long)blockIdx.z * sC;
    #pragma unroll
    for (int mt = 0; mt < 4; ++mt) {
        #pragma unroll
        for (int nt = 0; nt < 8; ++nt) {
            const long long m0 = bm + wm * 64 + mt * 16 + gr;
            const long long n  = bn + wn * 64 + nt * 8 + c2;
            const float* p1 = a1[mt][nt];
            float2 q0 = __half22float2(
                *reinterpret_cast<const __half2*>(&a2[mt][nt][0]));
            float2 q1 = __half22float2(
                *reinterpret_cast<const __half2*>(&a2[mt][nt][1]));
            float v[4];
            v[0] = p1[0] + (q0.x - p1[0]) * INV_C;
            v[1] = p1[1] + (q0.y - p1[1]) * INV_C;
            v[2] = p1[2] + (q1.x - p1[2]) * INV_C;
            v[3] = p1[3] + (q1.y - p1[3]) * INV_C;
            if (bias_mode == 1) {
                const float b0 = bias[n], b1 = bias[n + 1];
                v[0] += b0; v[1] += b1; v[2] += b0; v[3] += b1;
            } else {
                const float b0 = bias[m0], b1 = bias[m0 + 8];
                v[0] += b0; v[1] += b0; v[2] += b1; v[3] += b1;
            }
            *(uint32_t*)(Cb + m0 * N + n)       = packh2(v[0], v[1]);
            *(uint32_t*)(Cb + (m0 + 8) * N + n) = packh2(v[2], v[3]);
        }
    }
}

// =============== 1-pass GEMM: C = alpha * A@B^T (fp32 out) ===============
__global__ __launch_bounds__(256, 1)
void gemm_mma1(const __half* __restrict__ Ah, const __half* __restrict__ Bh,
               float* __restrict__ C,
               int M, int N, int K, float alpha,
               long long sA, long long sB, long long sC)
{
    extern __shared__ __align__(1024) char smem[];
    const uint32_t tb = smem_u32(smem);

    const int tid  = threadIdx.x;
    const int lane = tid & 31;
    const int wid  = tid >> 5;
    const int wm   = wid & 3;
    const int wn   = wid >> 2;

    const long long bm = (long long)blockIdx.y * TILE_M;
    const long long bn = (long long)blockIdx.x * TILE_N;
    Ah += (long long)blockIdx.z * sA + bm * K;
    Bh += (long long)blockIdx.z * sB + bn * K;

    const int ktot = K >> 5;

    auto load_tile = [&](int kt) {
        const int k0 = kt << 5;
        const uint32_t sbase = tb + (uint32_t)(kt % STAGES1) * STG_B1;
        #pragma unroll
        for (int rep = 0; rep < 4; ++rep) {
            const int ch  = tid + rep * 256;
            const int row = ch >> 2;
            const int c   = ch & 3;
            const size_t g = (size_t)row * K + k0 + c * 8;
            cp16(sbase + (uint32_t)(row * TSTRIDE + c * 8) * 2 + OFF_AH1, Ah + g);
        }
        #pragma unroll
        for (int rep = 0; rep < 2; ++rep) {
            const int ch  = tid + rep * 256;
            const int row = ch >> 2;
            const int c   = ch & 3;
            const size_t g = (size_t)row * K + k0 + c * 8;
            cp16(sbase + (uint32_t)(row * TSTRIDE + c * 8) * 2 + OFF_BH1, Bh + g);
        }
    };

    const int a_r = (lane & 7) + ((lane >> 3) & 1) * 8;
    const int a_k = (lane >> 4) * 8;
    const int b_n = (lane & 7) + ((lane >> 4) & 1) * 8;
    const int b_k = ((lane >> 3) & 1) * 8;

    float acc[4][8][4] = {};

    #pragma unroll
    for (int s = 0; s < STAGES1 - 1; ++s) {
        load_tile(s);
        asm volatile("cp.async.commit_group;" ::: "memory");
    }

    #pragma unroll 1
    for (int kt = 0; kt < ktot; ++kt) {
        asm volatile("cp.async.wait_group %0;" :: "n"(STAGES1 - 2) : "memory");
        __syncthreads();

        if (kt + STAGES1 - 1 < ktot) load_tile(kt + STAGES1 - 1);
        asm volatile("cp.async.commit_group;" ::: "memory");

        const uint32_t s0 = tb + (uint32_t)(kt % STAGES1) * STG_B1;
        #pragma unroll
        for (int k16 = 0; k16 < 2; ++k16) {
            uint32_t aH[4][4];
            #pragma unroll
            for (int mt = 0; mt < 4; ++mt) {
                const uint32_t off =
                    (uint32_t)((wm * 64 + mt * 16 + a_r) * TSTRIDE + k16 * 16 + a_k) * 2;
                ldsm4(aH[mt], s0 + OFF_AH1 + off);
            }
            #pragma unroll
            for (int j = 0; j < 4; ++j) {
                uint32_t bH[4];
                const uint32_t off =
                    (uint32_t)((wn * 64 + j * 16 + b_n) * TSTRIDE + k16 * 16 + b_k) * 2;
                ldsm4(bH, s0 + OFF_BH1 + off);
                #pragma unroll
                for (int mt = 0; mt < 4; ++mt) {
                    mma_f32(acc[mt][2 * j],     aH[mt], bH);
                    mma_f32(acc[mt][2 * j + 1], aH[mt], bH + 2);
                }
            }
        }
    }

    const int gr = lane >> 2;
    const int c2 = (lane & 3) * 2;
    float* Cb = C + (long long)blockIdx.z * sC;
    #pragma unroll
    for (int mt = 0; mt < 4; ++mt) {
        #pragma unroll
        for (int nt = 0; nt < 8; ++nt) {
            const long long m0 = bm + wm * 64 + mt * 16 + gr;
            const long long n  = bn + wn * 64 + nt * 8 + c2;
            const float* a4 = acc[mt][nt];
            *(float2*)(Cb + m0 * N + n) =
                make_float2(a4[0] * alpha, a4[1] * alpha);
            *(float2*)(Cb + (m0 + 8) * N + n) =
                make_float2(a4[2] * alpha, a4[3] * alpha);
        }
    }
}

// ---------------- fp32 -> fp16 (h, t) split ----------------
__global__ __launch_bounds__(256)
void split2(const float4* __restrict__ in, uint2* __restrict__ hp,
            uint2* __restrict__ tp, int n4)
{
    int i = blockIdx.x * 256 + threadIdx.x;
    if (i >= n4) return;
    float4 v = in[i];
    float h0, t0, h1, t1, h2, t2, h3, t3;
    split_ht(v.x, h0, t0); split_ht(v.y, h1, t1);
    split_ht(v.z, h2, t2); split_ht(v.w, h3, t3);
    hp[i] = make_uint2(packh2(h0, h1), packh2(h2, h3));
    tp[i] = make_uint2(packh2(t0, t1), packh2(t2, t3));
}

struct WArgs {
    const float4* in[3];
    uint2* hp[3];
    uint2* tp[3];
};
__global__ __launch_bounds__(256)
void splitW(WArgs a, int n4)
{
    const int w = blockIdx.y;
    int i = blockIdx.x * 256 + threadIdx.x;
    if (i >= n4) return;
    float4 v = a.in[w][i];
    float h0, t0, h1, t1, h2, t2, h3, t3;
    split_ht(v.x, h0, t0); split_ht(v.y, h1, t1);
    split_ht(v.z, h2, t2); split_ht(v.w, h3, t3);
    a.hp[w][i] = make_uint2(packh2(h0, h1), packh2(h2, h3));
    a.tp[w][i] = make_uint2(packh2(t0, t1), packh2(t2, t3));
}

// ---------------- softmax (fp32 in, fp16 out) ----------------
__global__ __launch_bounds__(256)
void softmax_h(const float* __restrict__ S, __half* __restrict__ P)
{
    const long long row = blockIdx.x;
    const float* p = S + row * (long long)SKc;
    const int t = threadIdx.x;

    float v[8];
    float mx = -3.402823466e38f;
    #pragma unroll
    for (int i = 0; i < 8; i++) {
        v[i] = p[t + i * 256];
        mx = fmaxf(mx, v[i]);
    }
    __shared__ float shm[8], shs[8];
    #pragma unroll
    for (int o = 16; o > 0; o >>= 1)
        mx = fmaxf(mx, __shfl_xor_sync(0xffffffffu, mx, o));
    if ((t & 31) == 0) shm[t >> 5] = mx;
    __syncthreads();
    mx = shm[0];
    #pragma unroll
    for (int w = 1; w < 8; w++) mx = fmaxf(mx, shm[w]);

    float sum = 0.f;
    #pragma unroll
    for (int i = 0; i < 8; i++) { v[i] = expf(v[i] - mx); sum += v[i]; }
    #pragma unroll
    for (int o = 16; o > 0; o >>= 1)
        sum += __shfl_xor_sync(0xffffffffu, sum, o);
    if ((t & 31) == 0) shs[t >> 5] = sum;
    __syncthreads();
    float tot = 0.f;
    #pragma unroll
    for (int w = 0; w < 8; w++) tot += shs[w];

    const float inv = 1.0f / tot;
    __half* ph = P + row * (long long)SKc;
    #pragma unroll
    for (int i = 0; i < 4; i++) {
        const float p0 = v[2 * i]     * inv;
        const float p1 = v[2 * i + 1] * inv;
        // adjacent elements handled by adjacent threads: keep original layout
        ph[t + (2 * i) * 256]     = __float2half_rn(p0);
        ph[t + (2 * i + 1) * 256] = __float2half_rn(p1);
    }
}

// ---------------- launch ----------------
extern "C" void kernel_launch(void* const* d_in, const int* in_sizes, int n_in,
                              void* d_out, int out_size)
{
    const float* x   = (const float*)d_in[0];
    const float* ctx = (const float*)d_in[1];
    const float* Wq  = (const float*)d_in[2];
    const float* bq  = (const float*)d_in[3];
    const float* Wk  = (const float*)d_in[4];
    const float* bk  = (const float*)d_in[5];
    const float* Wv  = (const float*)d_in[6];
    const float* bv  = (const float*)d_in[7];
    float* out = (float*)d_out;

    __half *xh, *xt, *ch, *ct, *Wqh, *Wqt, *Wkh, *Wkt, *Wvh, *Wvt;
    __half *Q, *Kp, *Vt, *P;
    float* S;
    cudaGetSymbolAddress((void**)&xh,  g_xh);  cudaGetSymbolAddress((void**)&xt,  g_xt);
    cudaGetSymbolAddress((void**)&ch,  g_ch);  cudaGetSymbolAddress((void**)&ct,  g_ct);
    cudaGetSymbolAddress((void**)&Wqh, g_Wqh); cudaGetSymbolAddress((void**)&Wqt, g_Wqt);
    cudaGetSymbolAddress((void**)&Wkh, g_Wkh); cudaGetSymbolAddress((void**)&Wkt, g_Wkt);
    cudaGetSymbolAddress((void**)&Wvh, g_Wvh); cudaGetSymbolAddress((void**)&Wvt, g_Wvt);
    cudaGetSymbolAddress((void**)&Q,   g_Q);
    cudaGetSymbolAddress((void**)&Kp,  g_K);
    cudaGetSymbolAddress((void**)&Vt,  g_Vt);
    cudaGetSymbolAddress((void**)&P,   g_P);
    cudaGetSymbolAddress((void**)&S,   g_S);

    cudaFuncSetAttribute(gemm_mma2, cudaFuncAttributeMaxDynamicSharedMemorySize, SMEM_B2);
    cudaFuncSetAttribute(gemm_mma1, cudaFuncAttributeMaxDynamicSharedMemorySize, SMEM_B1);

    const int n4x = (int)(NXQ / 4), n4w = DIMc * DIMc / 4;

    // 1,2: split activations
    split2<<<(n4x + 255) / 256, 256>>>((const float4*)x,   (uint2*)xh, (uint2*)xt, n4x);
    split2<<<(n4x + 255) / 256, 256>>>((const float4*)ctx, (uint2*)ch, (uint2*)ct, n4x);
    // 3: split weights
    WArgs wa;
    wa.in[0] = (const float4*)Wq; wa.hp[0] = (uint2*)Wqh; wa.tp[0] = (uint2*)Wqt;
    wa.in[1] = (const float4*)Wk; wa.hp[1] = (uint2*)Wkh; wa.tp[1] = (uint2*)Wkt;
    wa.in[2] = (const float4*)Wv; wa.hp[2] = (uint2*)Wvh; wa.tp[2] = (uint2*)Wvt;
    splitW<<<dim3((n4w + 255) / 256, 3), 256>>>(wa, n4w);

    const float scale = 0.03125f;   // 1/sqrt(1024)

    // 4: Q = fp16(x @ Wq^T + bq)
    gemm_mma2<<<dim3(DIMc / TILE_N, (NB * SQc) / TILE_M, 1), 256, SMEM_B2>>>(
        xh, xt, Wqh, Wqt, bq, 1, Q, NB * SQc, DIMc, DIMc, 0, 0, 0);
    // 5: K = fp16(ctx @ Wk^T + bk)
    gemm_mma2<<<dim3(DIMc / TILE_N, (NB * SKc) / TILE_M, 1), 256, SMEM_B2>>>(
        ch, ct, Wkh, Wkt, bk, 1, Kp, NB * SKc, DIMc, DIMc, 0, 0, 0);
    // 6: S = (Q @ K^T)/32  single-pass fp16, fp32 out   <- ncu window
    gemm_mma1<<<dim3(SKc / TILE_N, SQc / TILE_M, NB), 256, SMEM_B1>>>(
        Q, Kp, S, SQc, SKc, DIMc, scale,
        (long long)SQc * DIMc, (long long)SKc * DIMc, (long long)SQc * SKc);
    // 7: Vt = fp16(Wv @ ctx^T + bv(row))   per batch [1024, 2048]
    gemm_mma2<<<dim3(SKc / TILE_N, DIMc / TILE_M, NB), 256, SMEM_B2>>>(
        Wvh, Wvt, ch, ct, bv, 2, Vt,
        DIMc, SKc, DIMc, 0, (long long)SKc * DIMc, (long long)DIMc * SKc);
    // 8: softmax -> fp16 P
    softmax_h<<<NB * SQc, 256>>>(S, P);
    // 9: O = P @ Vt^T  single-pass fp16, fp32 out
    gemm_mma1<<<dim3(DIMc / TILE_N, SQc / TILE_M, NB), 256, SMEM_B1>>>(
        P, Vt, out, SQc, DIMc, SKc, 1.f,
        (long long)SQc * SKc, (long long)DIMc * SKc, (long long)SQc * DIMc);
}

// round 13
// speedup vs baseline: 2.4143x; 1.4015x over previous
#include <cuda_runtime.h>
#include <cuda_fp16.h>
#include <cstdint>

// CrossAttention B=8, SQ=SK=2048, DIM=1024, fp32 in/out.
// ALL GEMMs single-pass fp16 mma with fp32 accumulation (products exact in
// fp32 acc; error = fp16 input quantization ~3e-4, budget ~5e-4 total).
// Pipeline: cvt(x,ctx,W*) -> Q,K,Vt (fp16 out) -> S=QK^T/32 (fp32)
//           -> softmax (fp16 P) -> O = P@Vt^T (fp32).

#define DIMc 1024
#define NB   8
#define SQc  2048
#define SKc  2048

#define NXQ ((size_t)NB * SQc * DIMc)   // 16.7M
#define NS  ((size_t)NB * SQc * SKc)    // 33.5M

__device__ __align__(128) __half g_x[NXQ];
__device__ __align__(128) __half g_c[NXQ];
__device__ __align__(128) __half g_Wq[DIMc*DIMc];
__device__ __align__(128) __half g_Wk[DIMc*DIMc];
__device__ __align__(128) __half g_Wv[DIMc*DIMc];
__device__ __align__(128) __half g_Q[NXQ];
__device__ __align__(128) __half g_K[NXQ];
__device__ __align__(128) __half g_Vt[NXQ];
__device__ __align__(128) float  g_S[NS];
__device__ __align__(128) __half g_P[NS];

// ---------------- helpers ----------------
__device__ __forceinline__ uint32_t smem_u32(const void* p) {
    uint32_t a;
    asm("{ .reg .u64 t; cvta.to.shared.u64 t, %1; cvt.u32.u64 %0, t; }"
        : "=r"(a) : "l"(p));
    return a;
}
__device__ __forceinline__ void cp16(uint32_t dst, const void* src) {
    asm volatile("cp.async.cg.shared.global [%0], [%1], 16;"
                 :: "r"(dst), "l"(src));
}
__device__ __forceinline__ void ldsm4(uint32_t* r, uint32_t a) {
    asm volatile("ldmatrix.sync.aligned.m8n8.x4.shared.b16 {%0,%1,%2,%3}, [%4];"
                 : "=r"(r[0]), "=r"(r[1]), "=r"(r[2]), "=r"(r[3]) : "r"(a));
}
__device__ __forceinline__ void mma_f32(float* d, const uint32_t* a,
                                        const uint32_t* b) {
    asm volatile(
        "mma.sync.aligned.m16n8k16.row.col.f32.f16.f16.f32 "
        "{%0,%1,%2,%3}, {%4,%5,%6,%7}, {%8,%9}, {%0,%1,%2,%3};"
        : "+f"(d[0]), "+f"(d[1]), "+f"(d[2]), "+f"(d[3])
        : "r"(a[0]), "r"(a[1]), "r"(a[2]), "r"(a[3]), "r"(b[0]), "r"(b[1]));
}
__device__ __forceinline__ uint32_t packh2(float lo, float hi) {
    uint32_t r;
    asm("cvt.rn.f16x2.f32 %0, %1, %2;" : "=r"(r) : "f"(hi), "f"(lo));
    return r;
}

constexpr int TILE_M  = 256;
constexpr int TILE_N  = 128;
constexpr int STAGES  = 4;
constexpr int TSTRIDE = 40;                        // padded fp16 elems per row
constexpr int A_ARR_B = TILE_M * TSTRIDE * 2;      // 20480 B
constexpr int B_ARR_B = TILE_N * TSTRIDE * 2;      // 10240 B
constexpr int OFF_A   = 0;
constexpr int OFF_B   = A_ARR_B;
constexpr int STG_B   = A_ARR_B + B_ARR_B;         // 30720
constexpr int SMEM_B  = STAGES * STG_B;            // 122880

// ============ GEMM: C[M,N] = alpha * A[M,K] @ B[N,K]^T (+bias) ============
// OUTF16=0: fp32 C (alpha). OUTF16=1: fp16 Ch (bias added before round).
// bias_mode: 0 none, 1 per-column, 2 per-row.
template <int OUTF16>
__global__ __launch_bounds__(256, 1)
void gemm1(const __half* __restrict__ Ah, const __half* __restrict__ Bh,
           const float* __restrict__ bias, int bias_mode,
           float* __restrict__ C, __half* __restrict__ Ch,
           int M, int N, int K, float alpha,
           long long sA, long long sB, long long sC)
{
    extern __shared__ __align__(1024) char smem[];
    const uint32_t tb = smem_u32(smem);

    const int tid  = threadIdx.x;
    const int lane = tid & 31;
    const int wid  = tid >> 5;
    const int wm   = wid & 3;        // 4 warps along M (64 rows each)
    const int wn   = wid >> 2;       // 2 warps along N (64 cols each)

    const long long bm = (long long)blockIdx.y * TILE_M;
    const long long bn = (long long)blockIdx.x * TILE_N;
    Ah += (long long)blockIdx.z * sA + bm * K;
    Bh += (long long)blockIdx.z * sB + bn * K;

    const int ktot = K >> 5;

    auto load_tile = [&](int kt) {
        const int k0 = kt << 5;
        const uint32_t sbase = tb + (uint32_t)(kt % STAGES) * STG_B;
        #pragma unroll
        for (int rep = 0; rep < 4; ++rep) {
            const int ch  = tid + rep * 256;
            const int row = ch >> 2;
            const int c   = ch & 3;
            const size_t g = (size_t)row * K + k0 + c * 8;
            cp16(sbase + (uint32_t)(row * TSTRIDE + c * 8) * 2 + OFF_A, Ah + g);
        }
        #pragma unroll
        for (int rep = 0; rep < 2; ++rep) {
            const int ch  = tid + rep * 256;
            const int row = ch >> 2;
            const int c   = ch & 3;
            const size_t g = (size_t)row * K + k0 + c * 8;
            cp16(sbase + (uint32_t)(row * TSTRIDE + c * 8) * 2 + OFF_B, Bh + g);
        }
    };

    const int a_r = (lane & 7) + ((lane >> 3) & 1) * 8;
    const int a_k = (lane >> 4) * 8;
    const int b_n = (lane & 7) + ((lane >> 4) & 1) * 8;
    const int b_k = ((lane >> 3) & 1) * 8;

    float acc[4][8][4] = {};

    #pragma unroll
    for (int s = 0; s < STAGES - 1; ++s) {
        load_tile(s);
        asm volatile("cp.async.commit_group;" ::: "memory");
    }

    #pragma unroll 1
    for (int kt = 0; kt < ktot; ++kt) {
        asm volatile("cp.async.wait_group %0;" :: "n"(STAGES - 2) : "memory");
        __syncthreads();

        if (kt + STAGES - 1 < ktot) load_tile(kt + STAGES - 1);
        asm volatile("cp.async.commit_group;" ::: "memory");

        const uint32_t s0 = tb + (uint32_t)(kt % STAGES) * STG_B;
        #pragma unroll
        for (int k16 = 0; k16 < 2; ++k16) {
            uint32_t aH[4][4];
            #pragma unroll
            for (int mt = 0; mt < 4; ++mt) {
                const uint32_t off =
                    (uint32_t)((wm * 64 + mt * 16 + a_r) * TSTRIDE + k16 * 16 + a_k) * 2;
                ldsm4(aH[mt], s0 + OFF_A + off);
            }
            #pragma unroll
            for (int j = 0; j < 4; ++j) {
                uint32_t bH[4];
                const uint32_t off =
                    (uint32_t)((wn * 64 + j * 16 + b_n) * TSTRIDE + k16 * 16 + b_k) * 2;
                ldsm4(bH, s0 + OFF_B + off);
                #pragma unroll
                for (int mt = 0; mt < 4; ++mt) {
                    mma_f32(acc[mt][2 * j],     aH[mt], bH);
                    mma_f32(acc[mt][2 * j + 1], aH[mt], bH + 2);
                }
            }
        }
    }

    const int gr = lane >> 2;
    const int c2 = (lane & 3) * 2;
    #pragma unroll
    for (int mt = 0; mt < 4; ++mt) {
        #pragma unroll
        for (int nt = 0; nt < 8; ++nt) {
            const long long m0 = bm + wm * 64 + mt * 16 + gr;
            const long long n  = bn + wn * 64 + nt * 8 + c2;
            const float* a4 = acc[mt][nt];
            float v[4] = { a4[0], a4[1], a4[2], a4[3] };
            if (OUTF16 == 0) {
                float* Cb = C + (long long)blockIdx.z * sC;
                *(float2*)(Cb + m0 * N + n) =
                    make_float2(v[0] * alpha, v[1] * alpha);
                *(float2*)(Cb + (m0 + 8) * N + n) =
                    make_float2(v[2] * alpha, v[3] * alpha);
            } else {
                if (bias_mode == 1) {
                    const float b0 = bias[n], b1 = bias[n + 1];
                    v[0] += b0; v[1] += b1; v[2] += b0; v[3] += b1;
                } else if (bias_mode == 2) {
                    const float b0 = bias[m0], b1 = bias[m0 + 8];
                    v[0] += b0; v[1] += b0; v[2] += b1; v[3] += b1;
                }
                __half* Hb = Ch + (long long)blockIdx.z * sC;
                *(uint32_t*)(Hb + m0 * N + n)       = packh2(v[0], v[1]);
                *(uint32_t*)(Hb + (m0 + 8) * N + n) = packh2(v[2], v[3]);
            }
        }
    }
}

// ---------------- fp32 -> fp16 convert ----------------
__global__ __launch_bounds__(256)
void cvt16(const float4* __restrict__ in, uint2* __restrict__ hp, int n4)
{
    int i = blockIdx.x * 256 + threadIdx.x;
    if (i >= n4) return;
    float4 v = in[i];
    hp[i] = make_uint2(packh2(v.x, v.y), packh2(v.z, v.w));
}
struct WArgs {
    const float4* in[3];
    uint2* hp[3];
};
__global__ __launch_bounds__(256)
void cvtW(WArgs a, int n4)
{
    const int w = blockIdx.y;
    int i = blockIdx.x * 256 + threadIdx.x;
    if (i >= n4) return;
    float4 v = a.in[w][i];
    a.hp[w][i] = make_uint2(packh2(v.x, v.y), packh2(v.z, v.w));
}

// ---------------- softmax (fp32 in, fp16 out) ----------------
__global__ __launch_bounds__(256)
void softmax_h(const float* __restrict__ S, __half* __restrict__ P)
{
    const long long row = blockIdx.x;
    const float* p = S + row * (long long)SKc;
    const int t = threadIdx.x;

    float v[8];
    float mx = -3.402823466e38f;
    #pragma unroll
    for (int i = 0; i < 8; i++) {
        v[i] = p[t + i * 256];
        mx = fmaxf(mx, v[i]);
    }
    __shared__ float shm[8], shs[8];
    #pragma unroll
    for (int o = 16; o > 0; o >>= 1)
        mx = fmaxf(mx, __shfl_xor_sync(0xffffffffu, mx, o));
    if ((t & 31) == 0) shm[t >> 5] = mx;
    __syncthreads();
    mx = shm[0];
    #pragma unroll
    for (int w = 1; w < 8; w++) mx = fmaxf(mx, shm[w]);

    float sum = 0.f;
    #pragma unroll
    for (int i = 0; i < 8; i++) { v[i] = expf(v[i] - mx); sum += v[i]; }
    #pragma unroll
    for (int o = 16; o > 0; o >>= 1)
        sum += __shfl_xor_sync(0xffffffffu, sum, o);
    if ((t & 31) == 0) shs[t >> 5] = sum;
    __syncthreads();
    float tot = 0.f;
    #pragma unroll
    for (int w = 0; w < 8; w++) tot += shs[w];

    const float inv = 1.0f / tot;
    __half* ph = P + row * (long long)SKc;
    #pragma unroll
    for (int i = 0; i < 8; i++)
        ph[t + i * 256] = __float2half_rn(v[i] * inv);
}

// ---------------- launch ----------------
extern "C" void kernel_launch(void* const* d_in, const int* in_sizes, int n_in,
                              void* d_out, int out_size)
{
    const float* x   = (const float*)d_in[0];
    const float* ctx = (const float*)d_in[1];
    const float* Wq  = (const float*)d_in[2];
    const float* bq  = (const float*)d_in[3];
    const float* Wk  = (const float*)d_in[4];
    const float* bk  = (const float*)d_in[5];
    const float* Wv  = (const float*)d_in[6];
    const float* bv  = (const float*)d_in[7];
    float* out = (float*)d_out;

    __half *xh, *ch, *Wqh, *Wkh, *Wvh, *Q, *Kp, *Vt, *P;
    float* S;
    cudaGetSymbolAddress((void**)&xh,  g_x);
    cudaGetSymbolAddress((void**)&ch,  g_c);
    cudaGetSymbolAddress((void**)&Wqh, g_Wq);
    cudaGetSymbolAddress((void**)&Wkh, g_Wk);
    cudaGetSymbolAddress((void**)&Wvh, g_Wv);
    cudaGetSymbolAddress((void**)&Q,   g_Q);
    cudaGetSymbolAddress((void**)&Kp,  g_K);
    cudaGetSymbolAddress((void**)&Vt,  g_Vt);
    cudaGetSymbolAddress((void**)&P,   g_P);
    cudaGetSymbolAddress((void**)&S,   g_S);

    cudaFuncSetAttribute(gemm1<0>, cudaFuncAttributeMaxDynamicSharedMemorySize, SMEM_B);
    cudaFuncSetAttribute(gemm1<1>, cudaFuncAttributeMaxDynamicSharedMemorySize, SMEM_B);

    const int n4x = (int)(NXQ / 4), n4w = DIMc * DIMc / 4;

    // 1,2: convert activations; 3: convert weights
    cvt16<<<(n4x + 255) / 256, 256>>>((const float4*)x,   (uint2*)xh, n4x);
    cvt16<<<(n4x + 255) / 256, 256>>>((const float4*)ctx, (uint2*)ch, n4x);
    WArgs wa;
    wa.in[0] = (const float4*)Wq; wa.hp[0] = (uint2*)Wqh;
    wa.in[1] = (const float4*)Wk; wa.hp[1] = (uint2*)Wkh;
    wa.in[2] = (const float4*)Wv; wa.hp[2] = (uint2*)Wvh;
    cvtW<<<dim3((n4w + 255) / 256, 3), 256>>>(wa, n4w);

    const float scale = 0.03125f;   // 1/sqrt(1024)

    // 4: Q = fp16(x @ Wq^T + bq)
    gemm1<1><<<dim3(DIMc / TILE_N, (NB * SQc) / TILE_M, 1), 256, SMEM_B>>>(
        xh, Wqh, bq, 1, nullptr, Q, NB * SQc, DIMc, DIMc, 1.f, 0, 0, 0);
    // 5: K = fp16(ctx @ Wk^T + bk)
    gemm1<1><<<dim3(DIMc / TILE_N, (NB * SKc) / TILE_M, 1), 256, SMEM_B>>>(
        ch, Wkh, bk, 1, nullptr, Kp, NB * SKc, DIMc, DIMc, 1.f, 0, 0, 0);
    // 6: S = (Q @ K^T)/32  (fp32)   <- ncu window
    gemm1<0><<<dim3(SKc / TILE_N, SQc / TILE_M, NB), 256, SMEM_B>>>(
        Q, Kp, nullptr, 0, S, nullptr, SQc, SKc, DIMc, scale,
        (long long)SQc * DIMc, (long long)SKc * DIMc, (long long)SQc * SKc);
    // 7: Vt = fp16(Wv @ ctx^T + bv(row))   per batch [1024, 2048]
    gemm1<1><<<dim3(SKc / TILE_N, DIMc / TILE_M, NB), 256, SMEM_B>>>(
        Wvh, ch, bv, 2, nullptr, Vt, DIMc, SKc, DIMc, 1.f,
        0, (long long)SKc * DIMc, (long long)DIMc * SKc);
    // 8: softmax -> fp16 P
    softmax_h<<<NB * SQc, 256>>>(S, P);
    // 9: O = P @ Vt^T (fp32)
    gemm1<0><<<dim3(DIMc / TILE_N, SQc / TILE_M, NB), 256, SMEM_B>>>(
        P, Vt, nullptr, 0, out, nullptr, SQc, DIMc, SKc, 1.f,
        (long long)SQc * SKc, (long long)DIMc * SKc, (long long)SQc * DIMc);
}

// round 14
// speedup vs baseline: 2.6310x; 1.0898x over previous
#include <cuda_runtime.h>
#include <cuda_fp16.h>
#include <cstdint>

// CrossAttention B=8, SQ=SK=2048, DIM=1024, fp32 in/out.
// All GEMMs single-pass fp16 mma, fp32 accum (HW ceiling: 512 MAC/cyc/SM).
// R14: wave-quantization attack — merged projection launch (Q,K,Vt job table),
// PV retiled to 128x128/4-warp (2 CTA/SM), vectorized softmax.

#define DIMc 1024
#define NB   8
#define SQc  2048
#define SKc  2048

#define NXQ ((size_t)NB * SQc * DIMc)   // 16.7M
#define NS  ((size_t)NB * SQc * SKc)    // 33.5M

__device__ __align__(128) __half g_x[NXQ];
__device__ __align__(128) __half g_c[NXQ];
__device__ __align__(128) __half g_Wq[DIMc*DIMc];
__device__ __align__(128) __half g_Wk[DIMc*DIMc];
__device__ __align__(128) __half g_Wv[DIMc*DIMc];
__device__ __align__(128) __half g_Q[NXQ];
__device__ __align__(128) __half g_K[NXQ];
__device__ __align__(128) __half g_Vt[NXQ];
__device__ __align__(128) float  g_S[NS];
__device__ __align__(128) __half g_P[NS];

// ---------------- helpers ----------------
__device__ __forceinline__ uint32_t smem_u32(const void* p) {
    uint32_t a;
    asm("{ .reg .u64 t; cvta.to.shared.u64 t, %1; cvt.u32.u64 %0, t; }"
        : "=r"(a) : "l"(p));
    return a;
}
__device__ __forceinline__ void cp16(uint32_t dst, const void* src) {
    asm volatile("cp.async.cg.shared.global [%0], [%1], 16;"
                 :: "r"(dst), "l"(src));
}
__device__ __forceinline__ void ldsm4(uint32_t* r, uint32_t a) {
    asm volatile("ldmatrix.sync.aligned.m8n8.x4.shared.b16 {%0,%1,%2,%3}, [%4];"
                 : "=r"(r[0]), "=r"(r[1]), "=r"(r[2]), "=r"(r[3]) : "r"(a));
}
__device__ __forceinline__ void mma_f32(float* d, const uint32_t* a,
                                        const uint32_t* b) {
    asm volatile(
        "mma.sync.aligned.m16n8k16.row.col.f32.f16.f16.f32 "
        "{%0,%1,%2,%3}, {%4,%5,%6,%7}, {%8,%9}, {%0,%1,%2,%3};"
        : "+f"(d[0]), "+f"(d[1]), "+f"(d[2]), "+f"(d[3])
        : "r"(a[0]), "r"(a[1]), "r"(a[2]), "r"(a[3]), "r"(b[0]), "r"(b[1]));
}
__device__ __forceinline__ uint32_t packh2(float lo, float hi) {
    uint32_t r;
    asm("cvt.rn.f16x2.f32 %0, %1, %2;" : "=r"(r) : "f"(hi), "f"(lo));
    return r;
}

constexpr int TSTRIDE = 40;                        // padded fp16 elems per row

// ---- 256x128 / 8-warp config (S-GEMM + projections) ----
constexpr int TILE_M  = 256;
constexpr int TILE_N  = 128;
constexpr int STAGES  = 4;
constexpr int A_ARR_B = TILE_M * TSTRIDE * 2;      // 20480 B
constexpr int B_ARR_B = TILE_N * TSTRIDE * 2;      // 10240 B
constexpr int OFF_A   = 0;
constexpr int OFF_B   = A_ARR_B;
constexpr int STG_B   = A_ARR_B + B_ARR_B;         // 30720
constexpr int SMEM_B  = STAGES * STG_B;            // 122880

// ---- 128x128 / 4-warp config (PV) ----
constexpr int PV_ARR_B = 128 * TSTRIDE * 2;        // 10240
constexpr int PV_OFF_B = PV_ARR_B;
constexpr int PV_STG_B = 2 * PV_ARR_B;             // 20480
constexpr int PV_SMEM  = STAGES * PV_STG_B;        // 81920

// =============== S-GEMM: C = alpha * A[M,K] @ B[N,K]^T (fp32) ===============
__global__ __launch_bounds__(256, 1)
void gemm_s(const __half* __restrict__ Ah, const __half* __restrict__ Bh,
            float* __restrict__ C,
            int M, int N, int K, float alpha,
            long long sA, long long sB, long long sC)
{
    extern __shared__ __align__(1024) char smem[];
    const uint32_t tb = smem_u32(smem);

    const int tid  = threadIdx.x;
    const int lane = tid & 31;
    const int wid  = tid >> 5;
    const int wm   = wid & 3;
    const int wn   = wid >> 2;

    const long long bm = (long long)blockIdx.y * TILE_M;
    const long long bn = (long long)blockIdx.x * TILE_N;
    Ah += (long long)blockIdx.z * sA + bm * K;
    Bh += (long long)blockIdx.z * sB + bn * K;

    const int ktot = K >> 5;

    auto load_tile = [&](int kt) {
        const int k0 = kt << 5;
        const uint32_t sbase = tb + (uint32_t)(kt % STAGES) * STG_B;
        #pragma unroll
        for (int rep = 0; rep < 4; ++rep) {
            const int ch  = tid + rep * 256;
            const int row = ch >> 2;
            const int c   = ch & 3;
            const size_t g = (size_t)row * K + k0 + c * 8;
            cp16(sbase + (uint32_t)(row * TSTRIDE + c * 8) * 2 + OFF_A, Ah + g);
        }
        #pragma unroll
        for (int rep = 0; rep < 2; ++rep) {
            const int ch  = tid + rep * 256;
            const int row = ch >> 2;
            const int c   = ch & 3;
            const size_t g = (size_t)row * K + k0 + c * 8;
            cp16(sbase + (uint32_t)(row * TSTRIDE + c * 8) * 2 + OFF_B, Bh + g);
        }
    };

    const int a_r = (lane & 7) + ((lane >> 3) & 1) * 8;
    const int a_k = (lane >> 4) * 8;
    const int b_n = (lane & 7) + ((lane >> 4) & 1) * 8;
    const int b_k = ((lane >> 3) & 1) * 8;

    float acc[4][8][4] = {};

    #pragma unroll
    for (int s = 0; s < STAGES - 1; ++s) {
        load_tile(s);
        asm volatile("cp.async.commit_group;" ::: "memory");
    }

    #pragma unroll 1
    for (int kt = 0; kt < ktot; ++kt) {
        asm volatile("cp.async.wait_group %0;" :: "n"(STAGES - 2) : "memory");
        __syncthreads();
        if (kt + STAGES - 1 < ktot) load_tile(kt + STAGES - 1);
        asm volatile("cp.async.commit_group;" ::: "memory");

        const uint32_t s0 = tb + (uint32_t)(kt % STAGES) * STG_B;
        #pragma unroll
        for (int k16 = 0; k16 < 2; ++k16) {
            uint32_t aH[4][4];
            #pragma unroll
            for (int mt = 0; mt < 4; ++mt) {
                const uint32_t off =
                    (uint32_t)((wm * 64 + mt * 16 + a_r) * TSTRIDE + k16 * 16 + a_k) * 2;
                ldsm4(aH[mt], s0 + OFF_A + off);
            }
            #pragma unroll
            for (int j = 0; j < 4; ++j) {
                uint32_t bH[4];
                const uint32_t off =
                    (uint32_t)((wn * 64 + j * 16 + b_n) * TSTRIDE + k16 * 16 + b_k) * 2;
                ldsm4(bH, s0 + OFF_B + off);
                #pragma unroll
                for (int mt = 0; mt < 4; ++mt) {
                    mma_f32(acc[mt][2 * j],     aH[mt], bH);
                    mma_f32(acc[mt][2 * j + 1], aH[mt], bH + 2);
                }
            }
        }
    }

    const int gr = lane >> 2;
    const int c2 = (lane & 3) * 2;
    float* Cb = C + (long long)blockIdx.z * sC;
    #pragma unroll
    for (int mt = 0; mt < 4; ++mt) {
        #pragma unroll
        for (int nt = 0; nt < 8; ++nt) {
            const long long m0 = bm + wm * 64 + mt * 16 + gr;
            const long long n  = bn + wn * 64 + nt * 8 + c2;
            const float* a4 = acc[mt][nt];
            *(float2*)(Cb + m0 * N + n) =
                make_float2(a4[0] * alpha, a4[1] * alpha);
            *(float2*)(Cb + (m0 + 8) * N + n) =
                make_float2(a4[2] * alpha, a4[3] * alpha);
        }
    }
}

// ========== merged projections: Q, K, Vt in ONE launch (1536 CTAs) ==========
// id <  512 : Q  = fp16(x   @ Wq^T + bq)  [16384,1024] col-bias
// id < 1024 : K  = fp16(ctx @ Wk^T + bk)  [16384,1024] col-bias
// else      : Vt = fp16(Wv  @ ctx_b^T + bv) per batch [1024,2048] row-bias
struct ProjArgs {
    const __half *x, *c, *Wq, *Wk, *Wv;
    const float  *bq, *bk, *bv;
    __half *Q, *K, *Vt;
};
__global__ __launch_bounds__(256, 1)
void proj3(ProjArgs pa)
{
    extern __shared__ __align__(1024) char smem[];
    const uint32_t tb = smem_u32(smem);

    const int tid  = threadIdx.x;
    const int lane = tid & 31;
    const int wid  = tid >> 5;
    const int wm   = wid & 3;
    const int wn   = wid >> 2;

    const int id = blockIdx.x;
    const __half *Ah, *Bh;
    const float* bias;
    __half* Cc;
    long long bm, bn;
    int Nn, bias_row;

    if (id < 1024) {
        const bool isK = id >= 512;
        const int t = id & 511;
        bm = (long long)(t >> 3) * 256;
        bn = (long long)(t & 7) * 128;
        Ah = (isK ? pa.c : pa.x) + bm * DIMc;
        Bh = (isK ? pa.Wk : pa.Wq) + bn * DIMc;
        bias = isK ? pa.bk : pa.bq;
        Cc = isK ? pa.K : pa.Q;
        Nn = DIMc;
        bias_row = 0;
    } else {
        const int t = id - 1024;
        const int bz = t >> 6;
        const int rem = t & 63;
        bm = (long long)(rem >> 4) * 256;         // M=1024/256=4
        bn = (long long)(rem & 15) * 128;         // N=2048/128=16
        Ah = pa.Wv + bm * DIMc;
        Bh = pa.c + (long long)bz * SKc * DIMc + bn * DIMc;
        bias = pa.bv;
        Cc = pa.Vt + (long long)bz * DIMc * SKc;
        Nn = SKc;
        bias_row = 1;
    }

    const int ktot = DIMc >> 5;   // 32

    auto load_tile = [&](int kt) {
        const int k0 = kt << 5;
        const uint32_t sbase = tb + (uint32_t)(kt % STAGES) * STG_B;
        #pragma unroll
        for (int rep = 0; rep < 4; ++rep) {
            const int ch  = tid + rep * 256;
            const int row = ch >> 2;
            const int c   = ch & 3;
            const size_t g = (size_t)row * DIMc + k0 + c * 8;
            cp16(sbase + (uint32_t)(row * TSTRIDE + c * 8) * 2 + OFF_A, Ah + g);
        }
        #pragma unroll
        for (int rep = 0; rep < 2; ++rep) {
            const int ch  = tid + rep * 256;
            const int row = ch >> 2;
            const int c   = ch & 3;
            const size_t g = (size_t)row * DIMc + k0 + c * 8;
            cp16(sbase + (uint32_t)(row * TSTRIDE + c * 8) * 2 + OFF_B, Bh + g);
        }
    };

    const int a_r = (lane & 7) + ((lane >> 3) & 1) * 8;
    const int a_k = (lane >> 4) * 8;
    const int b_n = (lane & 7) + ((lane >> 4) & 1) * 8;
    const int b_k = ((lane >> 3) & 1) * 8;

    float acc[4][8][4] = {};

    #pragma unroll
    for (int s = 0; s < STAGES - 1; ++s) {
        load_tile(s);
        asm volatile("cp.async.commit_group;" ::: "memory");
    }

    #pragma unroll 1
    for (int kt = 0; kt < ktot; ++kt) {
        asm volatile("cp.async.wait_group %0;" :: "n"(STAGES - 2) : "memory");
        __syncthreads();
        if (kt + STAGES - 1 < ktot) load_tile(kt + STAGES - 1);
        asm volatile("cp.async.commit_group;" ::: "memory");

        const uint32_t s0 = tb + (uint32_t)(kt % STAGES) * STG_B;
        #pragma unroll
        for (int k16 = 0; k16 < 2; ++k16) {
            uint32_t aH[4][4];
            #pragma unroll
            for (int mt = 0; mt < 4; ++mt) {
                const uint32_t off =
                    (uint32_t)((wm * 64 + mt * 16 + a_r) * TSTRIDE + k16 * 16 + a_k) * 2;
                ldsm4(aH[mt], s0 + OFF_A + off);
            }
            #pragma unroll
            for (int j = 0; j < 4; ++j) {
                uint32_t bH[4];
                const uint32_t off =
                    (uint32_t)((wn * 64 + j * 16 + b_n) * TSTRIDE + k16 * 16 + b_k) * 2;
                ldsm4(bH, s0 + OFF_B + off);
                #pragma unroll
                for (int mt = 0; mt < 4; ++mt) {
                    mma_f32(acc[mt][2 * j],     aH[mt], bH);
                    mma_f32(acc[mt][2 * j + 1], aH[mt], bH + 2);
                }
            }
        }
    }

    const int gr = lane >> 2;
    const int c2 = (lane & 3) * 2;
    #pragma unroll
    for (int mt = 0; mt < 4; ++mt) {
        #pragma unroll
        for (int nt = 0; nt < 8; ++nt) {
            const long long m0 = bm + wm * 64 + mt * 16 + gr;
            const long long n  = bn + wn * 64 + nt * 8 + c2;
            const float* a4 = acc[mt][nt];
            float v[4] = { a4[0], a4[1], a4[2], a4[3] };
            if (bias_row) {
                const float b0 = bias[m0], b1 = bias[m0 + 8];
                v[0] += b0; v[1] += b0; v[2] += b1; v[3] += b1;
            } else {
                const float b0 = bias[n], b1 = bias[n + 1];
                v[0] += b0; v[1] += b1; v[2] += b0; v[3] += b1;
            }
            *(uint32_t*)(Cc + m0 * Nn + n)       = packh2(v[0], v[1]);
            *(uint32_t*)(Cc + (m0 + 8) * Nn + n) = packh2(v[2], v[3]);
        }
    }
}

// ========== PV GEMM: 128x128 tile, 4 warps, 2 CTA/SM (fp32 out) ==========
__global__ __launch_bounds__(128, 2)
void gemm_pv(const __half* __restrict__ Ah, const __half* __restrict__ Bh,
             float* __restrict__ C,
             int M, int N, int K,
             long long sA, long long sB, long long sC)
{
    extern __shared__ __align__(1024) char smem[];
    const uint32_t tb = smem_u32(smem);

    const int tid  = threadIdx.x;
    const int lane = tid & 31;
    const int wid  = tid >> 5;
    const int wm   = wid & 1;        // 2 warps along M (64 rows)
    const int wn   = wid >> 1;       // 2 warps along N (64 cols)

    const long long bm = (long long)blockIdx.y * 128;
    const long long bn = (long long)blockIdx.x * 128;
    Ah += (long long)blockIdx.z * sA + bm * K;
    Bh += (long long)blockIdx.z * sB + bn * K;

    const int ktot = K >> 5;

    auto load_tile = [&](int kt) {
        const int k0 = kt << 5;
        const uint32_t sbase = tb + (uint32_t)(kt % STAGES) * PV_STG_B;
        #pragma unroll
        for (int rep = 0; rep < 4; ++rep) {
            const int ch  = tid + rep * 128;
            const int row = ch >> 2;
            const int c   = ch & 3;
            const size_t g = (size_t)row * K + k0 + c * 8;
            cp16(sbase + (uint32_t)(row * TSTRIDE + c * 8) * 2, Ah + g);
        }
        #pragma unroll
        for (int rep = 0; rep < 4; ++rep) {
            const int ch  = tid + rep * 128;
            const int row = ch >> 2;
            const int c   = ch & 3;
            const size_t g = (size_t)row * K + k0 + c * 8;
            cp16(sbase + (uint32_t)(row * TSTRIDE + c * 8) * 2 + PV_OFF_B, Bh + g);
        }
    };

    const int a_r = (lane & 7) + ((lane >> 3) & 1) * 8;
    const int a_k = (lane >> 4) * 8;
    const int b_n = (lane & 7) + ((lane >> 4) & 1) * 8;
    const int b_k = ((lane >> 3) & 1) * 8;

    float acc[4][8][4] = {};

    #pragma unroll
    for (int s = 0; s < STAGES - 1; ++s) {
        load_tile(s);
        asm volatile("cp.async.commit_group;" ::: "memory");
    }

    #pragma unroll 1
    for (int kt = 0; kt < ktot; ++kt) {
        asm volatile("cp.async.wait_group %0;" :: "n"(STAGES - 2) : "memory");
        __syncthreads();
        if (kt + STAGES - 1 < ktot) load_tile(kt + STAGES - 1);
        asm volatile("cp.async.commit_group;" ::: "memory");

        const uint32_t s0 = tb + (uint32_t)(kt % STAGES) * PV_STG_B;
        #pragma unroll
        for (int k16 = 0; k16 < 2; ++k16) {
            uint32_t aH[4][4];
            #pragma unroll
            for (int mt = 0; mt < 4; ++mt) {
                const uint32_t off =
                    (uint32_t)((wm * 64 + mt * 16 + a_r) * TSTRIDE + k16 * 16 + a_k) * 2;
                ldsm4(aH[mt], s0 + off);
            }
            #pragma unroll
            for (int j = 0; j < 4; ++j) {
                uint32_t bH[4];
                const uint32_t off =
                    (uint32_t)((wn * 64 + j * 16 + b_n) * TSTRIDE + k16 * 16 + b_k) * 2;
                ldsm4(bH, s0 + PV_OFF_B + off);
                #pragma unroll
                for (int mt = 0; mt < 4; ++mt) {
                    mma_f32(acc[mt][2 * j],     aH[mt], bH);
                    mma_f32(acc[mt][2 * j + 1], aH[mt], bH + 2);
                }
            }
        }
    }

    const int gr = lane >> 2;
    const int c2 = (lane & 3) * 2;
    float* Cb = C + (long long)blockIdx.z * sC;
    #pragma unroll
    for (int mt = 0; mt < 4; ++mt) {
        #pragma unroll
        for (int nt = 0; nt < 8; ++nt) {
            const long long m0 = bm + wm * 64 + mt * 16 + gr;
            const long long n  = bn + wn * 64 + nt * 8 + c2;
            const float* a4 = acc[mt][nt];
            *(float2*)(Cb + m0 * N + n)       = make_float2(a4[0], a4[1]);
            *(float2*)(Cb + (m0 + 8) * N + n) = make_float2(a4[2], a4[3]);
        }
    }
}

// ---------------- fp32 -> fp16 convert ----------------
__global__ __launch_bounds__(256)
void cvt16(const float4* __restrict__ in, uint2* __restrict__ hp, int n4)
{
    int i = blockIdx.x * 256 + threadIdx.x;
    if (i >= n4) return;
    float4 v = in[i];
    hp[i] = make_uint2(packh2(v.x, v.y), packh2(v.z, v.w));
}
struct WArgs {
    const float4* in[3];
    uint2* hp[3];
};
__global__ __launch_bounds__(256)
void cvtW(WArgs a, int n4)
{
    const int w = blockIdx.y;
    int i = blockIdx.x * 256 + threadIdx.x;
    if (i >= n4) return;
    float4 v = a.in[w][i];
    a.hp[w][i] = make_uint2(packh2(v.x, v.y), packh2(v.z, v.w));
}

// ---------------- softmax (fp32 in, fp16 out, vectorized) ----------------
__global__ __launch_bounds__(256)
void softmax_h(const float* __restrict__ S, __half* __restrict__ P)
{
    const long long row = blockIdx.x;
    const float4* p = (const float4*)(S + row * (long long)SKc);
    const int t = threadIdx.x;

    float4 va = p[2 * t];
    float4 vb = p[2 * t + 1];
    float v[8] = { va.x, va.y, va.z, va.w, vb.x, vb.y, vb.z, vb.w };

    float mx = v[0];
    #pragma unroll
    for (int i = 1; i < 8; i++) mx = fmaxf(mx, v[i]);

    __shared__ float shm[8], shs[8];
    #pragma unroll
    for (int o = 16; o > 0; o >>= 1)
        mx = fmaxf(mx, __shfl_xor_sync(0xffffffffu, mx, o));
    if ((t & 31) == 0) shm[t >> 5] = mx;
    __syncthreads();
    mx = shm[0];
    #pragma unroll
    for (int w = 1; w < 8; w++) mx = fmaxf(mx, shm[w]);

    float sum = 0.f;
    #pragma unroll
    for (int i = 0; i < 8; i++) { v[i] = expf(v[i] - mx); sum += v[i]; }
    #pragma unroll
    for (int o = 16; o > 0; o >>= 1)
        sum += __shfl_xor_sync(0xffffffffu, sum, o);
    if ((t & 31) == 0) shs[t >> 5] = sum;
    __syncthreads();
    float tot = 0.f;
    #pragma unroll
    for (int w = 0; w < 8; w++) tot += shs[w];

    const float inv = 1.0f / tot;
    uint32_t* ph = (uint32_t*)(P + row * (long long)SKc) + 4 * t;
    #pragma unroll
    for (int i = 0; i < 4; i++)
        ph[i] = packh2(v[2 * i] * inv, v[2 * i + 1] * inv);
}

// ---------------- launch ----------------
extern "C" void kernel_launch(void* const* d_in, const int* in_sizes, int n_in,
                              void* d_out, int out_size)
{
    const float* x   = (const float*)d_in[0];
    const float* ctx = (const float*)d_in[1];
    const float* Wq  = (const float*)d_in[2];
    const float* bq  = (const float*)d_in[3];
    const float* Wk  = (const float*)d_in[4];
    const float* bk  = (const float*)d_in[5];
    const float* Wv  = (const float*)d_in[6];
    const float* bv  = (const float*)d_in[7];
    float* out = (float*)d_out;

    __half *xh, *ch, *Wqh, *Wkh, *Wvh, *Q, *Kp, *Vt, *P;
    float* S;
    cudaGetSymbolAddress((void**)&xh,  g_x);
    cudaGetSymbolAddress((void**)&ch,  g_c);
    cudaGetSymbolAddress((void**)&Wqh, g_Wq);
    cudaGetSymbolAddress((void**)&Wkh, g_Wk);
    cudaGetSymbolAddress((void**)&Wvh, g_Wv);
    cudaGetSymbolAddress((void**)&Q,   g_Q);
    cudaGetSymbolAddress((void**)&Kp,  g_K);
    cudaGetSymbolAddress((void**)&Vt,  g_Vt);
    cudaGetSymbolAddress((void**)&P,   g_P);
    cudaGetSymbolAddress((void**)&S,   g_S);

    cudaFuncSetAttribute(gemm_s,  cudaFuncAttributeMaxDynamicSharedMemorySize, SMEM_B);
    cudaFuncSetAttribute(proj3,   cudaFuncAttributeMaxDynamicSharedMemorySize, SMEM_B);
    cudaFuncSetAttribute(gemm_pv, cudaFuncAttributeMaxDynamicSharedMemorySize, PV_SMEM);

    const int n4x = (int)(NXQ / 4), n4w = DIMc * DIMc / 4;

    // 1-3: fp32 -> fp16 converts
    cvt16<<<(n4x + 255) / 256, 256>>>((const float4*)x,   (uint2*)xh, n4x);
    cvt16<<<(n4x + 255) / 256, 256>>>((const float4*)ctx, (uint2*)ch, n4x);
    WArgs wa;
    wa.in[0] = (const float4*)Wq; wa.hp[0] = (uint2*)Wqh;
    wa.in[1] = (const float4*)Wk; wa.hp[1] = (uint2*)Wkh;
    wa.in[2] = (const float4*)Wv; wa.hp[2] = (uint2*)Wvh;
    cvtW<<<dim3((n4w + 255) / 256, 3), 256>>>(wa, n4w);

    // 4: Q + K + Vt in one launch (1536 CTAs -> 11 waves instead of 12)
    ProjArgs pa;
    pa.x = xh; pa.c = ch; pa.Wq = Wqh; pa.Wk = Wkh; pa.Wv = Wvh;
    pa.bq = bq; pa.bk = bk; pa.bv = bv;
    pa.Q = Q; pa.K = Kp; pa.Vt = Vt;
    proj3<<<1536, 256, SMEM_B>>>(pa);

    const float scale = 0.03125f;   // 1/sqrt(1024)

    // 5: S = (Q @ K^T)/32  (fp32)
    gemm_s<<<dim3(SKc / TILE_N, SQc / TILE_M, NB), 256, SMEM_B>>>(
        Q, Kp, S, SQc, SKc, DIMc, scale,
        (long long)SQc * DIMc, (long long)SKc * DIMc, (long long)SQc * SKc);
    // 6: softmax -> fp16 P
    softmax_h<<<NB * SQc, 256>>>(S, P);
    // 7: O = P @ Vt^T  (128x128 tiles, 1024 CTAs -> 7 waves instead of 4 double-length)
    gemm_pv<<<dim3(DIMc / 128, SQc / 128, NB), 128, PV_SMEM>>>(
        P, Vt, out, SQc, DIMc, SKc,
        (long long)SQc * SKc, (long long)DIMc * SKc, (long long)SQc * DIMc);
}